// round 1
// baseline (speedup 1.0000x reference)
#include <cuda_runtime.h>
#include <cuda_bf16.h>
#include <math.h>

// Problem constants
#define S_LEN 2048
#define HID   4096
#define NH    32
#define NKV   8
#define HD    128
#define ROTD  64
#define RMS_EPS 1e-6f
#define ATT_SCALE 0.08838834764831843f  // 128^-0.5

// Scratch (static __device__ arrays: allocation-guard safe)
__device__ float g_q [S_LEN * NH  * HD];   // 32 MB
__device__ float g_k [S_LEN * NKV * HD];   //  8 MB
__device__ float g_v [S_LEN * NKV * HD];   //  8 MB
__device__ float g_ao[S_LEN * NH  * HD];   // 32 MB

// ---------------------------------------------------------------------------
// SGEMM: C[M,N] = A[M,K] @ B[N,K]^T   (both row-major, all dims % 128 == 0)
// 128x128 block tile, BK=8, 256 threads, 8x8 per-thread microtile (4+4 split)
// ---------------------------------------------------------------------------
__global__ __launch_bounds__(256) void sgemm_nt(
    const float* __restrict__ A, const float* __restrict__ B,
    float* __restrict__ C, int M, int N, int K)
{
    __shared__ float As[8][128];
    __shared__ float Bs[8][128];

    const int tid = threadIdx.x;
    const int bm = blockIdx.y * 128;
    const int bn = blockIdx.x * 128;

    const int lr = tid >> 1;          // 0..127: tile row to load
    const int lk = (tid & 1) * 4;     // 0 or 4: k offset within BK
    const int tx = tid & 15;
    const int ty = tid >> 4;

    const float* Ag = A + (size_t)(bm + lr) * K + lk;
    const float* Bg = B + (size_t)(bn + lr) * K + lk;

    float acc[8][8];
    #pragma unroll
    for (int i = 0; i < 8; i++)
        #pragma unroll
        for (int j = 0; j < 8; j++) acc[i][j] = 0.f;

    for (int k0 = 0; k0 < K; k0 += 8) {
        float4 av = *(const float4*)(Ag + k0);
        float4 bv = *(const float4*)(Bg + k0);
        As[lk + 0][lr] = av.x; As[lk + 1][lr] = av.y;
        As[lk + 2][lr] = av.z; As[lk + 3][lr] = av.w;
        Bs[lk + 0][lr] = bv.x; Bs[lk + 1][lr] = bv.y;
        Bs[lk + 2][lr] = bv.z; Bs[lk + 3][lr] = bv.w;
        __syncthreads();

        #pragma unroll
        for (int kk = 0; kk < 8; kk++) {
            float4 a0 = *(const float4*)&As[kk][ty * 4];
            float4 a1 = *(const float4*)&As[kk][ty * 4 + 64];
            float4 b0 = *(const float4*)&Bs[kk][tx * 4];
            float4 b1 = *(const float4*)&Bs[kk][tx * 4 + 64];
            float a[8] = {a0.x, a0.y, a0.z, a0.w, a1.x, a1.y, a1.z, a1.w};
            float b[8] = {b0.x, b0.y, b0.z, b0.w, b1.x, b1.y, b1.z, b1.w};
            #pragma unroll
            for (int i = 0; i < 8; i++)
                #pragma unroll
                for (int j = 0; j < 8; j++)
                    acc[i][j] = fmaf(a[i], b[j], acc[i][j]);
        }
        __syncthreads();
    }

    #pragma unroll
    for (int ii = 0; ii < 8; ii++) {
        int r = bm + ((ii < 4) ? (ty * 4 + ii) : (64 + ty * 4 + ii - 4));
        float4 c0 = make_float4(acc[ii][0], acc[ii][1], acc[ii][2], acc[ii][3]);
        float4 c1 = make_float4(acc[ii][4], acc[ii][5], acc[ii][6], acc[ii][7]);
        *(float4*)(C + (size_t)r * N + bn + tx * 4)      = c0;
        *(float4*)(C + (size_t)r * N + bn + 64 + tx * 4) = c1;
    }
}

// ---------------------------------------------------------------------------
// Fused per-head RMSNorm + partial RoPE (in place on g_q / g_k)
// One block (128 threads) per (token, head) vector.
// ---------------------------------------------------------------------------
__global__ __launch_bounds__(128) void norm_rope_kernel(
    const float* __restrict__ cosp, const float* __restrict__ sinp,
    const float* __restrict__ qw,   const float* __restrict__ kw)
{
    const int bid = blockIdx.x;
    const int d = threadIdx.x;            // 0..127
    const int lane = d & 31, wid = d >> 5;

    float* base;
    int s_idx;
    const float* w;
    if (bid < S_LEN * NH) {
        s_idx = bid / NH;
        base  = g_q + (size_t)bid * HD;
        w     = qw;
    } else {
        int b2 = bid - S_LEN * NH;
        s_idx = b2 / NKV;
        base  = g_k + (size_t)b2 * HD;
        w     = kw;
    }

    float x = base[d];

    // block sum of squares (128 threads)
    float v = x * x;
    #pragma unroll
    for (int o = 16; o > 0; o >>= 1) v += __shfl_xor_sync(0xffffffffu, v, o);
    __shared__ float red[4];
    __shared__ float xb[128];
    if (lane == 0) red[wid] = v;
    __syncthreads();
    float sum = red[0] + red[1] + red[2] + red[3];
    float rs = rsqrtf(sum * (1.0f / HD) + RMS_EPS);

    float xn = x * rs * w[d];
    xb[d] = xn;
    __syncthreads();

    float out;
    if (d < ROTD) {
        float c  = cosp[(size_t)s_idx * ROTD + d];
        float sn = sinp[(size_t)s_idx * ROTD + d];
        float partner = (d < 32) ? -xb[d + 32] : xb[d - 32];
        out = xn * c + partner * sn;
    } else {
        out = xn;
    }
    base[d] = out;
}

// ---------------------------------------------------------------------------
// Causal flash attention, fp32.  Grid: (32 q-tiles, 32 heads), 256 threads.
// BM=BN=64, D=128.  Q/K tiles stored d-major (transposed, pad 68),
// V row-major (pad 132), probs P (pad 68).  Dyn smem = 121600 B.
// ---------------------------------------------------------------------------
#define QK_STR 68
#define V_STR  132
#define P_STR  68

__global__ __launch_bounds__(256) void attn_kernel()
{
    extern __shared__ float sm[];
    float* Qt  = sm;                      // [128][68]
    float* Kt  = Qt + 128 * QK_STR;       // [128][68]
    float* Vs  = Kt + 128 * QK_STR;       // [64][132]
    float* Ps  = Vs + 64 * V_STR;         // [64][68]
    float* m_s = Ps + 64 * P_STR;         // [64]
    float* l_s = m_s + 64;                // [64]
    float* f_s = l_s + 64;                // [64]

    const int tid = threadIdx.x;
    const int qt  = blockIdx.x;           // q tile
    const int h   = blockIdx.y;           // head
    const int q0  = qt * 64;
    const int hk  = h >> 2;               // GQA: 4 q-heads per kv-head
    const int tx = tid & 15, ty = tid >> 4;

    // load Q tile transposed
    const float* gq = g_q + (size_t)q0 * (NH * HD) + h * HD;
    for (int t = tid; t < 64 * 32; t += 256) {
        int r = t >> 5;
        int d4 = (t & 31) << 2;
        float4 v = *(const float4*)(gq + (size_t)r * (NH * HD) + d4);
        Qt[(d4 + 0) * QK_STR + r] = v.x;
        Qt[(d4 + 1) * QK_STR + r] = v.y;
        Qt[(d4 + 2) * QK_STR + r] = v.z;
        Qt[(d4 + 3) * QK_STR + r] = v.w;
    }
    if (tid < 64) { m_s[tid] = -INFINITY; l_s[tid] = 0.f; }

    float o[4][8];
    #pragma unroll
    for (int i = 0; i < 4; i++)
        #pragma unroll
        for (int j = 0; j < 8; j++) o[i][j] = 0.f;

    for (int j = 0; j <= qt; j++) {
        __syncthreads();   // protect Kt/Vs reuse (and Q-load / stats-init on 1st iter)

        const float* gk = g_k + (size_t)(j * 64) * (NKV * HD) + hk * HD;
        const float* gv = g_v + (size_t)(j * 64) * (NKV * HD) + hk * HD;
        for (int t = tid; t < 64 * 32; t += 256) {
            int r = t >> 5;
            int d4 = (t & 31) << 2;
            float4 kv = *(const float4*)(gk + (size_t)r * (NKV * HD) + d4);
            Kt[(d4 + 0) * QK_STR + r] = kv.x;
            Kt[(d4 + 1) * QK_STR + r] = kv.y;
            Kt[(d4 + 2) * QK_STR + r] = kv.z;
            Kt[(d4 + 3) * QK_STR + r] = kv.w;
            float4 vv = *(const float4*)(gv + (size_t)r * (NKV * HD) + d4);
            *(float4*)(Vs + r * V_STR + d4) = vv;
        }
        __syncthreads();

        // S = Q K^T  (4x4 microtile per thread)
        float sacc[4][4];
        #pragma unroll
        for (int i = 0; i < 4; i++)
            #pragma unroll
            for (int jj = 0; jj < 4; jj++) sacc[i][jj] = 0.f;

        #pragma unroll 4
        for (int kk = 0; kk < 128; kk++) {
            float4 av = *(const float4*)(Qt + kk * QK_STR + (ty << 2));
            float4 bv = *(const float4*)(Kt + kk * QK_STR + (tx << 2));
            float a[4] = {av.x, av.y, av.z, av.w};
            float b[4] = {bv.x, bv.y, bv.z, bv.w};
            #pragma unroll
            for (int i = 0; i < 4; i++)
                #pragma unroll
                for (int jj = 0; jj < 4; jj++)
                    sacc[i][jj] = fmaf(a[i], b[jj], sacc[i][jj]);
        }

        // scale + causal mask on diagonal tile, store to Ps
        const bool diag = (j == qt);
        #pragma unroll
        for (int i = 0; i < 4; i++) {
            int r = ty * 4 + i;
            #pragma unroll
            for (int jj = 0; jj < 4; jj++) {
                int c = tx * 4 + jj;
                float sv = sacc[i][jj] * ATT_SCALE;
                if (diag && c > r) sv = -1e30f;
                Ps[r * P_STR + c] = sv;
            }
        }
        __syncthreads();

        // online softmax per row (64 rows on first 64 threads)
        if (tid < 64) {
            int r = tid;
            float mold = m_s[r];
            float mx = mold;
            #pragma unroll 8
            for (int c = 0; c < 64; c++) mx = fmaxf(mx, Ps[r * P_STR + c]);
            float f = __expf(mold - mx);
            float ssum = 0.f;
            #pragma unroll 8
            for (int c = 0; c < 64; c++) {
                float p = __expf(Ps[r * P_STR + c] - mx);
                Ps[r * P_STR + c] = p;
                ssum += p;
            }
            l_s[r] = l_s[r] * f + ssum;
            m_s[r] = mx;
            f_s[r] = f;
        }
        __syncthreads();

        // O = O*f + P @ V   (4 rows x 8 cols per thread)
        #pragma unroll
        for (int i = 0; i < 4; i++) {
            float f = f_s[ty * 4 + i];
            #pragma unroll
            for (int jj = 0; jj < 8; jj++) o[i][jj] *= f;
        }
        #pragma unroll 2
        for (int kk = 0; kk < 64; kk++) {
            float a[4];
            #pragma unroll
            for (int i = 0; i < 4; i++) a[i] = Ps[(ty * 4 + i) * P_STR + kk];
            float4 b0 = *(const float4*)(Vs + kk * V_STR + (tx << 3));
            float4 b1 = *(const float4*)(Vs + kk * V_STR + (tx << 3) + 4);
            float b[8] = {b0.x, b0.y, b0.z, b0.w, b1.x, b1.y, b1.z, b1.w};
            #pragma unroll
            for (int i = 0; i < 4; i++)
                #pragma unroll
                for (int jj = 0; jj < 8; jj++)
                    o[i][jj] = fmaf(a[i], b[jj], o[i][jj]);
        }
    }

    // epilogue: normalize and write
    #pragma unroll
    for (int i = 0; i < 4; i++) {
        int r = ty * 4 + i;
        float inv = 1.f / l_s[r];
        float4 w0 = make_float4(o[i][0] * inv, o[i][1] * inv, o[i][2] * inv, o[i][3] * inv);
        float4 w1 = make_float4(o[i][4] * inv, o[i][5] * inv, o[i][6] * inv, o[i][7] * inv);
        float* dst = g_ao + (size_t)(q0 + r) * (NH * HD) + h * HD + (tx << 3);
        *(float4*)(dst)     = w0;
        *(float4*)(dst + 4) = w1;
    }
}

// ---------------------------------------------------------------------------
// kernel_launch
// inputs: hidden, cos, sin, Wq, Wk, Wv, Wo, q_norm_w, k_norm_w
// ---------------------------------------------------------------------------
extern "C" void kernel_launch(void* const* d_in, const int* in_sizes, int n_in,
                              void* d_out, int out_size)
{
    const float* hidden = (const float*)d_in[0];
    const float* cosp   = (const float*)d_in[1];
    const float* sinp   = (const float*)d_in[2];
    const float* Wq     = (const float*)d_in[3];
    const float* Wk     = (const float*)d_in[4];
    const float* Wv     = (const float*)d_in[5];
    const float* Wo     = (const float*)d_in[6];
    const float* qw     = (const float*)d_in[7];
    const float* kw     = (const float*)d_in[8];
    float* out = (float*)d_out;

    float *qb, *kb, *vb, *aob;
    cudaGetSymbolAddress((void**)&qb,  g_q);
    cudaGetSymbolAddress((void**)&kb,  g_k);
    cudaGetSymbolAddress((void**)&vb,  g_v);
    cudaGetSymbolAddress((void**)&aob, g_ao);

    // QKV projections
    sgemm_nt<<<dim3(NH * HD / 128,  S_LEN / 128), 256>>>(hidden, Wq, qb, S_LEN, NH * HD,  HID);
    sgemm_nt<<<dim3(NKV * HD / 128, S_LEN / 128), 256>>>(hidden, Wk, kb, S_LEN, NKV * HD, HID);
    sgemm_nt<<<dim3(NKV * HD / 128, S_LEN / 128), 256>>>(hidden, Wv, vb, S_LEN, NKV * HD, HID);

    // per-head RMSNorm + RoPE (in place)
    norm_rope_kernel<<<S_LEN * (NH + NKV), 128>>>(cosp, sinp, qw, kw);

    // causal flash attention
    const int attn_smem = (2 * 128 * QK_STR + 64 * V_STR + 64 * P_STR + 3 * 64) * (int)sizeof(float);
    cudaFuncSetAttribute(attn_kernel, cudaFuncAttributeMaxDynamicSharedMemorySize, attn_smem);
    attn_kernel<<<dim3(S_LEN / 64, NH), 256, attn_smem>>>();

    // output projection -> d_out
    sgemm_nt<<<dim3(HID / 128, S_LEN / 128), 256>>>(aob, Wo, out, S_LEN, HID, NH * HD);
}

// round 2
// speedup vs baseline: 1.8226x; 1.8226x over previous
#include <cuda_runtime.h>
#include <cuda_bf16.h>
#include <math.h>
#include <stdint.h>

// Problem constants
#define S_LEN 2048
#define HID   4096
#define NH    32
#define NKV   8
#define HD    128
#define ROTD  64
#define RMS_EPS 1e-6f
#define ATT_SCALE 0.08838834764831843f  // 128^-0.5

// ---------------------------------------------------------------------------
// Scratch (static __device__ arrays: allocation-guard safe)
// ---------------------------------------------------------------------------
__device__ float g_q [S_LEN * NH  * HD];   // 32 MB
__device__ float g_k [S_LEN * NKV * HD];   //  8 MB
__device__ float g_v [S_LEN * NKV * HD];   //  8 MB
__device__ float g_ao[S_LEN * NH  * HD];   // 32 MB

// bf16 hi/lo split buffers
__device__ __nv_bfloat16 g_hid_h[S_LEN * HID];
__device__ __nv_bfloat16 g_hid_l[S_LEN * HID];
__device__ __nv_bfloat16 g_wq_h [NH * HD * HID];
__device__ __nv_bfloat16 g_wq_l [NH * HD * HID];
__device__ __nv_bfloat16 g_wk_h [NKV * HD * HID];
__device__ __nv_bfloat16 g_wk_l [NKV * HD * HID];
__device__ __nv_bfloat16 g_wv_h [NKV * HD * HID];
__device__ __nv_bfloat16 g_wv_l [NKV * HD * HID];
__device__ __nv_bfloat16 g_wo_h [HID * NH * HD];
__device__ __nv_bfloat16 g_wo_l [HID * NH * HD];
__device__ __nv_bfloat16 g_ao_h [S_LEN * NH * HD];
__device__ __nv_bfloat16 g_ao_l [S_LEN * NH * HD];

// ---------------------------------------------------------------------------
// fp32 -> (bf16 hi, bf16 lo) split conversion, 4 elems/thread
// ---------------------------------------------------------------------------
__global__ __launch_bounds__(256) void cvt_split(
    const float* __restrict__ x, __nv_bfloat16* __restrict__ hi,
    __nv_bfloat16* __restrict__ lo, int n)
{
    int i = (blockIdx.x * 256 + threadIdx.x) * 4;
    if (i >= n) return;
    float4 v = *(const float4*)(x + i);
    __nv_bfloat16 h[4], l[4];
    float vv[4] = {v.x, v.y, v.z, v.w};
    #pragma unroll
    for (int j = 0; j < 4; j++) {
        h[j] = __float2bfloat16(vv[j]);
        l[j] = __float2bfloat16(vv[j] - __bfloat162float(h[j]));
    }
    *(uint2*)(hi + i) = *(uint2*)h;
    *(uint2*)(lo + i) = *(uint2*)l;
}

// ---------------------------------------------------------------------------
// bf16-split tensor-core GEMM (NT): C[M,N] = A[M,K] @ B[N,K]^T  in ~fp32 acc.
// C = Ah@Bh + Ah@Bl + Al@Bh.  128x128x32 tiles, 256 thr, 2-stage cp.async.
// smem per stage: 4 matrices x 128 rows x stride 40 bf16 = 40960 B.
// ---------------------------------------------------------------------------
#define SSTR 40
#define STAGE_B 40960u  // bytes per stage
#define MAT_B  10240u   // bytes per matrix within stage

__device__ __forceinline__ void cp16(uint32_t s, const void* g) {
    asm volatile("cp.async.cg.shared.global [%0], [%1], 16;\n"
                 :: "r"(s), "l"(g) : "memory");
}
__device__ __forceinline__ void ldsm4(uint32_t& r0, uint32_t& r1,
                                      uint32_t& r2, uint32_t& r3, uint32_t a) {
    asm volatile("ldmatrix.sync.aligned.m8n8.x4.shared.b16 {%0,%1,%2,%3}, [%4];\n"
                 : "=r"(r0), "=r"(r1), "=r"(r2), "=r"(r3) : "r"(a));
}
__device__ __forceinline__ void mma16816(float* c, const uint32_t* a,
                                         uint32_t b0, uint32_t b1) {
    asm volatile(
        "mma.sync.aligned.m16n8k16.row.col.f32.bf16.bf16.f32 "
        "{%0,%1,%2,%3}, {%4,%5,%6,%7}, {%8,%9}, {%0,%1,%2,%3};\n"
        : "+f"(c[0]), "+f"(c[1]), "+f"(c[2]), "+f"(c[3])
        : "r"(a[0]), "r"(a[1]), "r"(a[2]), "r"(a[3]), "r"(b0), "r"(b1));
}

__global__ __launch_bounds__(256) void gemm_bf16split(
    const __nv_bfloat16* __restrict__ Ah, const __nv_bfloat16* __restrict__ Al,
    const __nv_bfloat16* __restrict__ Bh, const __nv_bfloat16* __restrict__ Bl,
    float* __restrict__ C, int M, int N, int K)
{
    extern __shared__ __nv_bfloat16 smem[];
    const int tid  = threadIdx.x;
    const int lane = tid & 31, warp = tid >> 5;
    const int wm = (warp & 3) * 32;          // warp m offset within block tile
    const int wn = (warp >> 2) * 64;         // warp n offset
    const size_t bm = (size_t)blockIdx.y * 128;
    const size_t bn = (size_t)blockIdx.x * 128;

    const int lrow = tid >> 2;               // 0..63 (load row)
    const int lch  = (tid & 3) * 8;          // bf16 offset within BK row

    uint32_t sbase = (uint32_t)__cvta_generic_to_shared(smem);
    const uint32_t sthis = 2u * (uint32_t)(lrow * SSTR + lch);  // byte offset of my chunk

    const __nv_bfloat16* gAh = Ah + (bm + lrow) * K + lch;
    const __nv_bfloat16* gAl = Al + (bm + lrow) * K + lch;
    const __nv_bfloat16* gBh = Bh + (bn + lrow) * K + lch;
    const __nv_bfloat16* gBl = Bl + (bn + lrow) * K + lch;
    const size_t rstep = (size_t)64 * K;     // +64 rows in gmem
    const uint32_t srstep = 2u * 64 * SSTR;  // +64 rows in smem (bytes)

    float acc[2][8][4];
    #pragma unroll
    for (int i = 0; i < 2; i++)
        #pragma unroll
        for (int j = 0; j < 8; j++)
            #pragma unroll
            for (int k = 0; k < 4; k++) acc[i][j][k] = 0.f;

    const int niter = K / 32;

    auto issue = [&](int it) {
        const int st = it & 1;
        const uint32_t s = sbase + st * STAGE_B + sthis;
        const int k0 = it * 32;
        cp16(s,                       gAh + k0);
        cp16(s + srstep,              gAh + k0 + rstep);
        cp16(s + MAT_B,               gAl + k0);
        cp16(s + MAT_B + srstep,      gAl + k0 + rstep);
        cp16(s + 2 * MAT_B,           gBh + k0);
        cp16(s + 2 * MAT_B + srstep,  gBh + k0 + rstep);
        cp16(s + 3 * MAT_B,           gBl + k0);
        cp16(s + 3 * MAT_B + srstep,  gBl + k0 + rstep);
        asm volatile("cp.async.commit_group;\n" ::: "memory");
    };

    issue(0);
    // precompute lane pieces for ldmatrix addressing
    const int a_r  = lane & 15;                       // A row-in-16
    const int b_r  = (lane & 7) + ((lane >> 3) & 1) * 8;  // B row-in-16
    const int khl  = (lane >> 4) * 8;                 // k half

    for (int it = 0; it < niter; ++it) {
        if (it + 1 < niter) issue(it + 1);
        if (it + 1 < niter)
            asm volatile("cp.async.wait_group 1;\n" ::: "memory");
        else
            asm volatile("cp.async.wait_group 0;\n" ::: "memory");
        __syncthreads();

        const uint32_t sb = sbase + (it & 1) * STAGE_B;
        #pragma unroll
        for (int kk = 0; kk < 32; kk += 16) {
            uint32_t ah[2][4], al[2][4];
            #pragma unroll
            for (int mb = 0; mb < 2; mb++) {
                uint32_t addr = sb + 2u * (uint32_t)((wm + mb * 16 + a_r) * SSTR + kk + khl);
                ldsm4(ah[mb][0], ah[mb][1], ah[mb][2], ah[mb][3], addr);
                ldsm4(al[mb][0], al[mb][1], al[mb][2], al[mb][3], addr + MAT_B);
            }
            uint32_t bh[4][4], bl[4][4];
            #pragma unroll
            for (int nb = 0; nb < 4; nb++) {
                uint32_t addr = sb + 2u * MAT_B +
                    2u * (uint32_t)((wn + nb * 16 + b_r) * SSTR + kk + khl);
                ldsm4(bh[nb][0], bh[nb][1], bh[nb][2], bh[nb][3], addr);
                ldsm4(bl[nb][0], bl[nb][1], bl[nb][2], bl[nb][3], addr + MAT_B);
            }
            #pragma unroll
            for (int mb = 0; mb < 2; mb++) {
                #pragma unroll
                for (int n8 = 0; n8 < 8; n8++) {
                    const int nb = n8 >> 1, w = n8 & 1;
                    // block0: regs {0,2}; block1: regs {1,3}
                    uint32_t bh0 = bh[nb][w], bh1 = bh[nb][w + 2];
                    uint32_t bl0 = bl[nb][w], bl1 = bl[nb][w + 2];
                    mma16816(acc[mb][n8], ah[mb], bh0, bh1);
                    mma16816(acc[mb][n8], ah[mb], bl0, bl1);
                    mma16816(acc[mb][n8], al[mb], bh0, bh1);
                }
            }
        }
        __syncthreads();
    }

    // epilogue
    #pragma unroll
    for (int mb = 0; mb < 2; mb++) {
        const size_t row = bm + wm + mb * 16 + (lane >> 2);
        #pragma unroll
        for (int n8 = 0; n8 < 8; n8++) {
            const size_t col = bn + wn + n8 * 8 + (lane & 3) * 2;
            *(float2*)&C[row * N + col] = make_float2(acc[mb][n8][0], acc[mb][n8][1]);
            *(float2*)&C[(row + 8) * N + col] = make_float2(acc[mb][n8][2], acc[mb][n8][3]);
        }
    }
}

// ---------------------------------------------------------------------------
// Fused per-head RMSNorm + partial RoPE (in place on g_q / g_k)
// ---------------------------------------------------------------------------
__global__ __launch_bounds__(128) void norm_rope_kernel(
    const float* __restrict__ cosp, const float* __restrict__ sinp,
    const float* __restrict__ qw,   const float* __restrict__ kw)
{
    const int bid = blockIdx.x;
    const int d = threadIdx.x;            // 0..127
    const int lane = d & 31, wid = d >> 5;

    float* base;
    int s_idx;
    const float* w;
    if (bid < S_LEN * NH) {
        s_idx = bid / NH;
        base  = g_q + (size_t)bid * HD;
        w     = qw;
    } else {
        int b2 = bid - S_LEN * NH;
        s_idx = b2 / NKV;
        base  = g_k + (size_t)b2 * HD;
        w     = kw;
    }

    float x = base[d];
    float v = x * x;
    #pragma unroll
    for (int o = 16; o > 0; o >>= 1) v += __shfl_xor_sync(0xffffffffu, v, o);
    __shared__ float red[4];
    __shared__ float xb[128];
    if (lane == 0) red[wid] = v;
    __syncthreads();
    float sum = red[0] + red[1] + red[2] + red[3];
    float rs = rsqrtf(sum * (1.0f / HD) + RMS_EPS);

    float xn = x * rs * w[d];
    xb[d] = xn;
    __syncthreads();

    float out;
    if (d < ROTD) {
        float c  = cosp[(size_t)s_idx * ROTD + d];
        float sn = sinp[(size_t)s_idx * ROTD + d];
        float partner = (d < 32) ? -xb[d + 32] : xb[d - 32];
        out = xn * c + partner * sn;
    } else {
        out = xn;
    }
    base[d] = out;
}

// ---------------------------------------------------------------------------
// Causal flash attention, fp32 SIMT (unchanged from R1; correct baseline)
// ---------------------------------------------------------------------------
#define QK_STR 68
#define V_STR  132
#define P_STR  68

__global__ __launch_bounds__(256) void attn_kernel()
{
    extern __shared__ float sm[];
    float* Qt  = sm;                      // [128][68]
    float* Kt  = Qt + 128 * QK_STR;       // [128][68]
    float* Vs  = Kt + 128 * QK_STR;       // [64][132]
    float* Ps  = Vs + 64 * V_STR;         // [64][68]
    float* m_s = Ps + 64 * P_STR;         // [64]
    float* l_s = m_s + 64;
    float* f_s = l_s + 64;

    const int tid = threadIdx.x;
    const int qt  = blockIdx.x;
    const int h   = blockIdx.y;
    const int q0  = qt * 64;
    const int hk  = h >> 2;
    const int tx = tid & 15, ty = tid >> 4;

    const float* gq = g_q + (size_t)q0 * (NH * HD) + h * HD;
    for (int t = tid; t < 64 * 32; t += 256) {
        int r = t >> 5;
        int d4 = (t & 31) << 2;
        float4 v = *(const float4*)(gq + (size_t)r * (NH * HD) + d4);
        Qt[(d4 + 0) * QK_STR + r] = v.x;
        Qt[(d4 + 1) * QK_STR + r] = v.y;
        Qt[(d4 + 2) * QK_STR + r] = v.z;
        Qt[(d4 + 3) * QK_STR + r] = v.w;
    }
    if (tid < 64) { m_s[tid] = -INFINITY; l_s[tid] = 0.f; }

    float o[4][8];
    #pragma unroll
    for (int i = 0; i < 4; i++)
        #pragma unroll
        for (int j = 0; j < 8; j++) o[i][j] = 0.f;

    for (int j = 0; j <= qt; j++) {
        __syncthreads();

        const float* gk = g_k + (size_t)(j * 64) * (NKV * HD) + hk * HD;
        const float* gv = g_v + (size_t)(j * 64) * (NKV * HD) + hk * HD;
        for (int t = tid; t < 64 * 32; t += 256) {
            int r = t >> 5;
            int d4 = (t & 31) << 2;
            float4 kv = *(const float4*)(gk + (size_t)r * (NKV * HD) + d4);
            Kt[(d4 + 0) * QK_STR + r] = kv.x;
            Kt[(d4 + 1) * QK_STR + r] = kv.y;
            Kt[(d4 + 2) * QK_STR + r] = kv.z;
            Kt[(d4 + 3) * QK_STR + r] = kv.w;
            float4 vv = *(const float4*)(gv + (size_t)r * (NKV * HD) + d4);
            *(float4*)(Vs + r * V_STR + d4) = vv;
        }
        __syncthreads();

        float sacc[4][4];
        #pragma unroll
        for (int i = 0; i < 4; i++)
            #pragma unroll
            for (int jj = 0; jj < 4; jj++) sacc[i][jj] = 0.f;

        #pragma unroll 4
        for (int kk = 0; kk < 128; kk++) {
            float4 av = *(const float4*)(Qt + kk * QK_STR + (ty << 2));
            float4 bv = *(const float4*)(Kt + kk * QK_STR + (tx << 2));
            float a[4] = {av.x, av.y, av.z, av.w};
            float b[4] = {bv.x, bv.y, bv.z, bv.w};
            #pragma unroll
            for (int i = 0; i < 4; i++)
                #pragma unroll
                for (int jj = 0; jj < 4; jj++)
                    sacc[i][jj] = fmaf(a[i], b[jj], sacc[i][jj]);
        }

        const bool diag = (j == qt);
        #pragma unroll
        for (int i = 0; i < 4; i++) {
            int r = ty * 4 + i;
            #pragma unroll
            for (int jj = 0; jj < 4; jj++) {
                int c = tx * 4 + jj;
                float sv = sacc[i][jj] * ATT_SCALE;
                if (diag && c > r) sv = -1e30f;
                Ps[r * P_STR + c] = sv;
            }
        }
        __syncthreads();

        if (tid < 64) {
            int r = tid;
            float mold = m_s[r];
            float mx = mold;
            #pragma unroll 8
            for (int c = 0; c < 64; c++) mx = fmaxf(mx, Ps[r * P_STR + c]);
            float f = __expf(mold - mx);
            float ssum = 0.f;
            #pragma unroll 8
            for (int c = 0; c < 64; c++) {
                float p = __expf(Ps[r * P_STR + c] - mx);
                Ps[r * P_STR + c] = p;
                ssum += p;
            }
            l_s[r] = l_s[r] * f + ssum;
            m_s[r] = mx;
            f_s[r] = f;
        }
        __syncthreads();

        #pragma unroll
        for (int i = 0; i < 4; i++) {
            float f = f_s[ty * 4 + i];
            #pragma unroll
            for (int jj = 0; jj < 8; jj++) o[i][jj] *= f;
        }
        #pragma unroll 2
        for (int kk = 0; kk < 64; kk++) {
            float a[4];
            #pragma unroll
            for (int i = 0; i < 4; i++) a[i] = Ps[(ty * 4 + i) * P_STR + kk];
            float4 b0 = *(const float4*)(Vs + kk * V_STR + (tx << 3));
            float4 b1 = *(const float4*)(Vs + kk * V_STR + (tx << 3) + 4);
            float b[8] = {b0.x, b0.y, b0.z, b0.w, b1.x, b1.y, b1.z, b1.w};
            #pragma unroll
            for (int i = 0; i < 4; i++)
                #pragma unroll
                for (int jj = 0; jj < 8; jj++)
                    o[i][jj] = fmaf(a[i], b[jj], o[i][jj]);
        }
    }

    #pragma unroll
    for (int i = 0; i < 4; i++) {
        int r = ty * 4 + i;
        float inv = 1.f / l_s[r];
        float4 w0 = make_float4(o[i][0] * inv, o[i][1] * inv, o[i][2] * inv, o[i][3] * inv);
        float4 w1 = make_float4(o[i][4] * inv, o[i][5] * inv, o[i][6] * inv, o[i][7] * inv);
        float* dst = g_ao + (size_t)(q0 + r) * (NH * HD) + h * HD + (tx << 3);
        *(float4*)(dst)     = w0;
        *(float4*)(dst + 4) = w1;
    }
}

// ---------------------------------------------------------------------------
// kernel_launch
// ---------------------------------------------------------------------------
extern "C" void kernel_launch(void* const* d_in, const int* in_sizes, int n_in,
                              void* d_out, int out_size)
{
    const float* hidden = (const float*)d_in[0];
    const float* cosp   = (const float*)d_in[1];
    const float* sinp   = (const float*)d_in[2];
    const float* Wq     = (const float*)d_in[3];
    const float* Wk     = (const float*)d_in[4];
    const float* Wv     = (const float*)d_in[5];
    const float* Wo     = (const float*)d_in[6];
    const float* qw     = (const float*)d_in[7];
    const float* kw     = (const float*)d_in[8];
    float* out = (float*)d_out;

    float *qb, *kb, *vb, *aob;
    cudaGetSymbolAddress((void**)&qb,  g_q);
    cudaGetSymbolAddress((void**)&kb,  g_k);
    cudaGetSymbolAddress((void**)&vb,  g_v);
    cudaGetSymbolAddress((void**)&aob, g_ao);
    __nv_bfloat16 *hid_h, *hid_l, *wq_h, *wq_l, *wk_h, *wk_l, *wv_h, *wv_l;
    __nv_bfloat16 *wo_h, *wo_l, *ao_h, *ao_l;
    cudaGetSymbolAddress((void**)&hid_h, g_hid_h);
    cudaGetSymbolAddress((void**)&hid_l, g_hid_l);
    cudaGetSymbolAddress((void**)&wq_h,  g_wq_h);
    cudaGetSymbolAddress((void**)&wq_l,  g_wq_l);
    cudaGetSymbolAddress((void**)&wk_h,  g_wk_h);
    cudaGetSymbolAddress((void**)&wk_l,  g_wk_l);
    cudaGetSymbolAddress((void**)&wv_h,  g_wv_h);
    cudaGetSymbolAddress((void**)&wv_l,  g_wv_l);
    cudaGetSymbolAddress((void**)&wo_h,  g_wo_h);
    cudaGetSymbolAddress((void**)&wo_l,  g_wo_l);
    cudaGetSymbolAddress((void**)&ao_h,  g_ao_h);
    cudaGetSymbolAddress((void**)&ao_l,  g_ao_l);

    // split conversions
    {
        int n;
        n = S_LEN * HID;      cvt_split<<<n / 1024, 256>>>(hidden, hid_h, hid_l, n);
        n = NH * HD * HID;    cvt_split<<<n / 1024, 256>>>(Wq, wq_h, wq_l, n);
        n = NKV * HD * HID;   cvt_split<<<n / 1024, 256>>>(Wk, wk_h, wk_l, n);
        n = NKV * HD * HID;   cvt_split<<<n / 1024, 256>>>(Wv, wv_h, wv_l, n);
        n = HID * NH * HD;    cvt_split<<<n / 1024, 256>>>(Wo, wo_h, wo_l, n);
    }

    const int gemm_smem = 2 * 40960;
    cudaFuncSetAttribute(gemm_bf16split, cudaFuncAttributeMaxDynamicSharedMemorySize, gemm_smem);

    // QKV projections (tensor cores)
    gemm_bf16split<<<dim3(NH * HD / 128,  S_LEN / 128), 256, gemm_smem>>>(
        hid_h, hid_l, wq_h, wq_l, qb, S_LEN, NH * HD,  HID);
    gemm_bf16split<<<dim3(NKV * HD / 128, S_LEN / 128), 256, gemm_smem>>>(
        hid_h, hid_l, wk_h, wk_l, kb, S_LEN, NKV * HD, HID);
    gemm_bf16split<<<dim3(NKV * HD / 128, S_LEN / 128), 256, gemm_smem>>>(
        hid_h, hid_l, wv_h, wv_l, vb, S_LEN, NKV * HD, HID);

    // per-head RMSNorm + RoPE (in place)
    norm_rope_kernel<<<S_LEN * (NH + NKV), 128>>>(cosp, sinp, qw, kw);

    // causal flash attention (fp32)
    const int attn_smem = (2 * 128 * QK_STR + 64 * V_STR + 64 * P_STR + 3 * 64) * (int)sizeof(float);
    cudaFuncSetAttribute(attn_kernel, cudaFuncAttributeMaxDynamicSharedMemorySize, attn_smem);
    attn_kernel<<<dim3(S_LEN / 64, NH), 256, attn_smem>>>();

    // split attention output, then O projection (tensor cores)
    {
        int n = S_LEN * NH * HD;
        cvt_split<<<n / 1024, 256>>>(aob, ao_h, ao_l, n);
    }
    gemm_bf16split<<<dim3(HID / 128, S_LEN / 128), 256, gemm_smem>>>(
        ao_h, ao_l, wo_h, wo_l, out, S_LEN, HID, NH * HD);
}

// round 3
// speedup vs baseline: 2.7719x; 1.5209x over previous
#include <cuda_runtime.h>
#include <cuda_bf16.h>
#include <math.h>
#include <stdint.h>

// Problem constants
#define S_LEN 2048
#define HID   4096
#define NH    32
#define NKV   8
#define HD    128
#define ROTD  64
#define RMS_EPS 1e-6f
#define ATT_SCALE 0.08838834764831843f  // 128^-0.5

#define SEGQ  (S_LEN * NH * HD)    // 8388608
#define SEGKV (S_LEN * NKV * HD)   // 2097152

// ---------------------------------------------------------------------------
// Scratch
// ---------------------------------------------------------------------------
__device__ float g_q [S_LEN * NH  * HD];
__device__ float g_k [S_LEN * NKV * HD];
__device__ float g_v [S_LEN * NKV * HD];

// bf16 hi/lo split buffers
__device__ __nv_bfloat16 g_hid_h[S_LEN * HID];
__device__ __nv_bfloat16 g_hid_l[S_LEN * HID];
__device__ __nv_bfloat16 g_wq_h [NH * HD * HID];
__device__ __nv_bfloat16 g_wq_l [NH * HD * HID];
__device__ __nv_bfloat16 g_wk_h [NKV * HD * HID];
__device__ __nv_bfloat16 g_wk_l [NKV * HD * HID];
__device__ __nv_bfloat16 g_wv_h [NKV * HD * HID];
__device__ __nv_bfloat16 g_wv_l [NKV * HD * HID];
__device__ __nv_bfloat16 g_wo_h [HID * NH * HD];
__device__ __nv_bfloat16 g_wo_l [HID * NH * HD];

// attention operand splits: [hi seg | lo seg] contiguous
__device__ __nv_bfloat16 g_qsplit [2 * SEGQ];        // post norm+rope Q
__device__ __nv_bfloat16 g_kvsplit[4 * SEGKV];       // Kh | Kl | Vh | Vl
__device__ __nv_bfloat16 g_aosplit[2 * SEGQ];        // attention out hi|lo

// ---------------------------------------------------------------------------
// fp32 -> (bf16 hi, bf16 lo) split, 4 elems/thread
// ---------------------------------------------------------------------------
__global__ __launch_bounds__(256) void cvt_split(
    const float* __restrict__ x, __nv_bfloat16* __restrict__ hi,
    __nv_bfloat16* __restrict__ lo, int n)
{
    int i = (blockIdx.x * 256 + threadIdx.x) * 4;
    if (i >= n) return;
    float4 v = *(const float4*)(x + i);
    __nv_bfloat16 h[4], l[4];
    float vv[4] = {v.x, v.y, v.z, v.w};
    #pragma unroll
    for (int j = 0; j < 4; j++) {
        h[j] = __float2bfloat16(vv[j]);
        l[j] = __float2bfloat16(vv[j] - __bfloat162float(h[j]));
    }
    *(uint2*)(hi + i) = *(uint2*)h;
    *(uint2*)(lo + i) = *(uint2*)l;
}

// ---------------------------------------------------------------------------
// PTX helpers
// ---------------------------------------------------------------------------
__device__ __forceinline__ void cp16(uint32_t s, const void* g) {
    asm volatile("cp.async.cg.shared.global [%0], [%1], 16;\n"
                 :: "r"(s), "l"(g) : "memory");
}
__device__ __forceinline__ void ldsm4(uint32_t& r0, uint32_t& r1,
                                      uint32_t& r2, uint32_t& r3, uint32_t a) {
    asm volatile("ldmatrix.sync.aligned.m8n8.x4.shared.b16 {%0,%1,%2,%3}, [%4];\n"
                 : "=r"(r0), "=r"(r1), "=r"(r2), "=r"(r3) : "r"(a));
}
__device__ __forceinline__ void ldsm4t(uint32_t& r0, uint32_t& r1,
                                       uint32_t& r2, uint32_t& r3, uint32_t a) {
    asm volatile("ldmatrix.sync.aligned.m8n8.x4.trans.shared.b16 {%0,%1,%2,%3}, [%4];\n"
                 : "=r"(r0), "=r"(r1), "=r"(r2), "=r"(r3) : "r"(a));
}
__device__ __forceinline__ void mma16816(float* c, const uint32_t* a,
                                         uint32_t b0, uint32_t b1) {
    asm volatile(
        "mma.sync.aligned.m16n8k16.row.col.f32.bf16.bf16.f32 "
        "{%0,%1,%2,%3}, {%4,%5,%6,%7}, {%8,%9}, {%0,%1,%2,%3};\n"
        : "+f"(c[0]), "+f"(c[1]), "+f"(c[2]), "+f"(c[3])
        : "r"(a[0]), "r"(a[1]), "r"(a[2]), "r"(a[3]), "r"(b0), "r"(b1));
}
__device__ __forceinline__ uint32_t packbf2(__nv_bfloat16 x, __nv_bfloat16 y) {
    __nv_bfloat162 t; t.x = x; t.y = y;
    return *(uint32_t*)&t;
}

// ---------------------------------------------------------------------------
// bf16-split tensor-core GEMM (NT): unchanged from R2
// ---------------------------------------------------------------------------
#define SSTR 40
#define STAGE_B 40960u
#define MAT_B  10240u

__global__ __launch_bounds__(256) void gemm_bf16split(
    const __nv_bfloat16* __restrict__ Ah, const __nv_bfloat16* __restrict__ Al,
    const __nv_bfloat16* __restrict__ Bh, const __nv_bfloat16* __restrict__ Bl,
    float* __restrict__ C, int M, int N, int K)
{
    extern __shared__ __nv_bfloat16 smem[];
    const int tid  = threadIdx.x;
    const int lane = tid & 31, warp = tid >> 5;
    const int wm = (warp & 3) * 32;
    const int wn = (warp >> 2) * 64;
    const size_t bm = (size_t)blockIdx.y * 128;
    const size_t bn = (size_t)blockIdx.x * 128;

    const int lrow = tid >> 2;
    const int lch  = (tid & 3) * 8;

    uint32_t sbase = (uint32_t)__cvta_generic_to_shared(smem);
    const uint32_t sthis = 2u * (uint32_t)(lrow * SSTR + lch);

    const __nv_bfloat16* gAh = Ah + (bm + lrow) * K + lch;
    const __nv_bfloat16* gAl = Al + (bm + lrow) * K + lch;
    const __nv_bfloat16* gBh = Bh + (bn + lrow) * K + lch;
    const __nv_bfloat16* gBl = Bl + (bn + lrow) * K + lch;
    const size_t rstep = (size_t)64 * K;
    const uint32_t srstep = 2u * 64 * SSTR;

    float acc[2][8][4];
    #pragma unroll
    for (int i = 0; i < 2; i++)
        #pragma unroll
        for (int j = 0; j < 8; j++)
            #pragma unroll
            for (int k = 0; k < 4; k++) acc[i][j][k] = 0.f;

    const int niter = K / 32;

    auto issue = [&](int it) {
        const int st = it & 1;
        const uint32_t s = sbase + st * STAGE_B + sthis;
        const int k0 = it * 32;
        cp16(s,                       gAh + k0);
        cp16(s + srstep,              gAh + k0 + rstep);
        cp16(s + MAT_B,               gAl + k0);
        cp16(s + MAT_B + srstep,      gAl + k0 + rstep);
        cp16(s + 2 * MAT_B,           gBh + k0);
        cp16(s + 2 * MAT_B + srstep,  gBh + k0 + rstep);
        cp16(s + 3 * MAT_B,           gBl + k0);
        cp16(s + 3 * MAT_B + srstep,  gBl + k0 + rstep);
        asm volatile("cp.async.commit_group;\n" ::: "memory");
    };

    issue(0);
    const int a_r  = lane & 15;
    const int b_r  = (lane & 7) + ((lane >> 3) & 1) * 8;
    const int khl  = (lane >> 4) * 8;

    for (int it = 0; it < niter; ++it) {
        if (it + 1 < niter) issue(it + 1);
        if (it + 1 < niter)
            asm volatile("cp.async.wait_group 1;\n" ::: "memory");
        else
            asm volatile("cp.async.wait_group 0;\n" ::: "memory");
        __syncthreads();

        const uint32_t sb = sbase + (it & 1) * STAGE_B;
        #pragma unroll
        for (int kk = 0; kk < 32; kk += 16) {
            uint32_t ah[2][4], al[2][4];
            #pragma unroll
            for (int mb = 0; mb < 2; mb++) {
                uint32_t addr = sb + 2u * (uint32_t)((wm + mb * 16 + a_r) * SSTR + kk + khl);
                ldsm4(ah[mb][0], ah[mb][1], ah[mb][2], ah[mb][3], addr);
                ldsm4(al[mb][0], al[mb][1], al[mb][2], al[mb][3], addr + MAT_B);
            }
            uint32_t bh[4][4], bl[4][4];
            #pragma unroll
            for (int nb = 0; nb < 4; nb++) {
                uint32_t addr = sb + 2u * MAT_B +
                    2u * (uint32_t)((wn + nb * 16 + b_r) * SSTR + kk + khl);
                ldsm4(bh[nb][0], bh[nb][1], bh[nb][2], bh[nb][3], addr);
                ldsm4(bl[nb][0], bl[nb][1], bl[nb][2], bl[nb][3], addr + MAT_B);
            }
            #pragma unroll
            for (int mb = 0; mb < 2; mb++) {
                #pragma unroll
                for (int n8 = 0; n8 < 8; n8++) {
                    const int nb = n8 >> 1, w = n8 & 1;
                    uint32_t bh0 = bh[nb][w], bh1 = bh[nb][w + 2];
                    uint32_t bl0 = bl[nb][w], bl1 = bl[nb][w + 2];
                    mma16816(acc[mb][n8], ah[mb], bh0, bh1);
                    mma16816(acc[mb][n8], ah[mb], bl0, bl1);
                    mma16816(acc[mb][n8], al[mb], bh0, bh1);
                }
            }
        }
        __syncthreads();
    }

    #pragma unroll
    for (int mb = 0; mb < 2; mb++) {
        const size_t row = bm + wm + mb * 16 + (lane >> 2);
        #pragma unroll
        for (int n8 = 0; n8 < 8; n8++) {
            const size_t col = bn + wn + n8 * 8 + (lane & 3) * 2;
            *(float2*)&C[row * N + col] = make_float2(acc[mb][n8][0], acc[mb][n8][1]);
            *(float2*)&C[(row + 8) * N + col] = make_float2(acc[mb][n8][2], acc[mb][n8][3]);
        }
    }
}

// ---------------------------------------------------------------------------
// Fused per-head RMSNorm + partial RoPE: reads fp32 q/k, writes bf16 hi/lo
// ---------------------------------------------------------------------------
__global__ __launch_bounds__(128) void norm_rope_kernel(
    const float* __restrict__ cosp, const float* __restrict__ sinp,
    const float* __restrict__ qw,   const float* __restrict__ kw)
{
    const int bid = blockIdx.x;
    const int d = threadIdx.x;
    const int lane = d & 31, wid = d >> 5;

    const float* base;
    __nv_bfloat16 *dst_h, *dst_l;
    int s_idx;
    const float* w;
    size_t idx;
    if (bid < S_LEN * NH) {
        s_idx = bid / NH;
        idx   = (size_t)bid * HD + d;
        base  = g_q + (size_t)bid * HD;
        dst_h = g_qsplit;  dst_l = g_qsplit + SEGQ;
        w     = qw;
    } else {
        int b2 = bid - S_LEN * NH;
        s_idx = b2 / NKV;
        idx   = (size_t)b2 * HD + d;
        base  = g_k + (size_t)b2 * HD;
        dst_h = g_kvsplit; dst_l = g_kvsplit + SEGKV;
        w     = kw;
    }

    float x = base[d];
    float v = x * x;
    #pragma unroll
    for (int o = 16; o > 0; o >>= 1) v += __shfl_xor_sync(0xffffffffu, v, o);
    __shared__ float red[4];
    __shared__ float xb[128];
    if (lane == 0) red[wid] = v;
    __syncthreads();
    float sum = red[0] + red[1] + red[2] + red[3];
    float rs = rsqrtf(sum * (1.0f / HD) + RMS_EPS);

    float xn = x * rs * w[d];
    xb[d] = xn;
    __syncthreads();

    float out;
    if (d < ROTD) {
        float c  = cosp[(size_t)s_idx * ROTD + d];
        float sn = sinp[(size_t)s_idx * ROTD + d];
        float partner = (d < 32) ? -xb[d + 32] : xb[d - 32];
        out = xn * c + partner * sn;
    } else {
        out = xn;
    }
    __nv_bfloat16 h = __float2bfloat16(out);
    dst_h[idx] = h;
    dst_l[idx] = __float2bfloat16(out - __bfloat162float(h));
}

// ---------------------------------------------------------------------------
// Tensor-core causal flash attention (bf16 hi/lo split).
// BM=128 (8 warps x 16 rows), BN=64, D=128, 256 threads.
// smem: Qh,Ql [128][136]; double-buffered Kh,Kl,Vh,Vl [64][136]. 208896 B.
// ---------------------------------------------------------------------------
#define ASTR 136
#define QMAT (128 * ASTR)   // 17408 elems
#define AMAT (64 * ASTR)    // 8704 elems
#define ATT_SMEM ((2 * QMAT + 8 * AMAT) * 2)  // bytes = 208896

__global__ __launch_bounds__(256) void attn_mma_kernel()
{
    extern __shared__ __nv_bfloat16 sh[];
    const uint32_t sbase = (uint32_t)__cvta_generic_to_shared(sh);

    const int tid  = threadIdx.x;
    const int lane = tid & 31, w = tid >> 5;
    const int qtile = (S_LEN / 128 - 1) - blockIdx.x;   // largest first
    const int h  = blockIdx.y;
    const int hk = h >> 2;
    const int q0 = qtile * 128;
    const int qrow0 = q0 + w * 16;
    const int jmax = 2 * qtile + 1;

    const int b_r = (lane & 7) + ((lane >> 3) & 1) * 8;
    const int khl = (lane >> 4) * 8;
    const int r   = lane >> 2;

    // ---- async loads ----
    auto load_q = [&]() {
        #pragma unroll
        for (int i = 0; i < 16; i++) {
            int c   = tid + i * 256;      // 0..4095
            int mat = c >> 11;            // 0:hi 1:lo
            int rem = c & 2047;
            int row = rem >> 4, col = rem & 15;
            const __nv_bfloat16* src = g_qsplit + (size_t)mat * SEGQ +
                ((size_t)(q0 + row) * NH + h) * HD + col * 8;
            uint32_t dst = sbase + (uint32_t)(mat * QMAT + row * ASTR) * 2 + col * 16;
            cp16(dst, src);
        }
    };
    auto load_kv = [&](int j) {
        const int kvb = 2 * QMAT + (j & 1) * 4 * AMAT;
        #pragma unroll
        for (int i = 0; i < 16; i++) {
            int c   = tid + i * 256;      // 0..4095
            int mat = c >> 10;            // 0:Kh 1:Kl 2:Vh 3:Vl
            int rem = c & 1023;
            int row = rem >> 4, col = rem & 15;
            const __nv_bfloat16* src = g_kvsplit + (size_t)mat * SEGKV +
                ((size_t)(j * 64 + row) * NKV + hk) * HD + col * 8;
            uint32_t dst = sbase + (uint32_t)(kvb + mat * AMAT + row * ASTR) * 2 + col * 16;
            cp16(dst, src);
        }
    };

    load_q();
    load_kv(0);
    asm volatile("cp.async.commit_group;\n" ::: "memory");

    float oacc[16][4];
    #pragma unroll
    for (int i = 0; i < 16; i++)
        #pragma unroll
        for (int e = 0; e < 4; e++) oacc[i][e] = 0.f;
    float m0 = -INFINITY, m1 = -INFINITY, l0 = 0.f, l1 = 0.f;

    for (int j = 0; j <= jmax; j++) {
        const bool ahead = (j + 1 <= jmax);
        if (ahead) {
            load_kv(j + 1);
            asm volatile("cp.async.commit_group;\n" ::: "memory");
            asm volatile("cp.async.wait_group 1;\n" ::: "memory");
        } else {
            asm volatile("cp.async.wait_group 0;\n" ::: "memory");
        }
        __syncthreads();

        const bool active = (j * 64 <= qrow0 + 15);
        if (active) {
            const int kvb = 2 * QMAT + (j & 1) * 4 * AMAT;

            // ---- S = Q K^T (3-term split) ----
            float sacc[8][4];
            #pragma unroll
            for (int b = 0; b < 8; b++)
                #pragma unroll
                for (int e = 0; e < 4; e++) sacc[b][e] = 0.f;

            #pragma unroll
            for (int k0 = 0; k0 < 8; k0++) {
                uint32_t qaddr = sbase +
                    (uint32_t)((w * 16 + (lane & 15)) * ASTR + k0 * 16 + 8 * (lane >> 4)) * 2;
                uint32_t aqh[4], aql[4];
                ldsm4(aqh[0], aqh[1], aqh[2], aqh[3], qaddr);
                ldsm4(aql[0], aql[1], aql[2], aql[3], qaddr + QMAT * 2);
                #pragma unroll
                for (int nb = 0; nb < 4; nb++) {
                    uint32_t kaddr = sbase +
                        (uint32_t)(kvb + (nb * 16 + b_r) * ASTR + k0 * 16 + khl) * 2;
                    uint32_t kh[4], kl[4];
                    ldsm4(kh[0], kh[1], kh[2], kh[3], kaddr);
                    ldsm4(kl[0], kl[1], kl[2], kl[3], kaddr + AMAT * 2);
                    mma16816(sacc[2 * nb],     aqh, kh[0], kh[2]);
                    mma16816(sacc[2 * nb + 1], aqh, kh[1], kh[3]);
                    mma16816(sacc[2 * nb],     aqh, kl[0], kl[2]);
                    mma16816(sacc[2 * nb + 1], aqh, kl[1], kl[3]);
                    mma16816(sacc[2 * nb],     aql, kh[0], kh[2]);
                    mma16816(sacc[2 * nb + 1], aql, kh[1], kh[3]);
                }
            }

            // ---- scale + causal mask ----
            const bool full = (j * 64 + 63 <= qrow0);
            #pragma unroll
            for (int b = 0; b < 8; b++)
                #pragma unroll
                for (int e = 0; e < 4; e++) sacc[b][e] *= ATT_SCALE;
            if (!full) {
                #pragma unroll
                for (int b = 0; b < 8; b++) {
                    int colb = j * 64 + b * 8 + 2 * (lane & 3);
                    int rlo = qrow0 + r, rhi = rlo + 8;
                    if (colb     > rlo) sacc[b][0] = -1e30f;
                    if (colb + 1 > rlo) sacc[b][1] = -1e30f;
                    if (colb     > rhi) sacc[b][2] = -1e30f;
                    if (colb + 1 > rhi) sacc[b][3] = -1e30f;
                }
            }

            // ---- online softmax (rows r, r+8) ----
            float mx0 = -INFINITY, mx1 = -INFINITY;
            #pragma unroll
            for (int b = 0; b < 8; b++) {
                mx0 = fmaxf(mx0, fmaxf(sacc[b][0], sacc[b][1]));
                mx1 = fmaxf(mx1, fmaxf(sacc[b][2], sacc[b][3]));
            }
            mx0 = fmaxf(mx0, __shfl_xor_sync(0xffffffffu, mx0, 1));
            mx0 = fmaxf(mx0, __shfl_xor_sync(0xffffffffu, mx0, 2));
            mx1 = fmaxf(mx1, __shfl_xor_sync(0xffffffffu, mx1, 1));
            mx1 = fmaxf(mx1, __shfl_xor_sync(0xffffffffu, mx1, 2));
            float mn0 = fmaxf(m0, mx0), mn1 = fmaxf(m1, mx1);
            float f0 = __expf(m0 - mn0), f1 = __expf(m1 - mn1);
            m0 = mn0; m1 = mn1;

            float s0 = 0.f, s1 = 0.f;
            #pragma unroll
            for (int b = 0; b < 8; b++) {
                sacc[b][0] = __expf(sacc[b][0] - mn0);
                sacc[b][1] = __expf(sacc[b][1] - mn0);
                sacc[b][2] = __expf(sacc[b][2] - mn1);
                sacc[b][3] = __expf(sacc[b][3] - mn1);
                s0 += sacc[b][0] + sacc[b][1];
                s1 += sacc[b][2] + sacc[b][3];
            }
            s0 += __shfl_xor_sync(0xffffffffu, s0, 1);
            s0 += __shfl_xor_sync(0xffffffffu, s0, 2);
            s1 += __shfl_xor_sync(0xffffffffu, s1, 1);
            s1 += __shfl_xor_sync(0xffffffffu, s1, 2);
            l0 = l0 * f0 + s0;
            l1 = l1 * f1 + s1;

            #pragma unroll
            for (int nb = 0; nb < 16; nb++) {
                oacc[nb][0] *= f0; oacc[nb][1] *= f0;
                oacc[nb][2] *= f1; oacc[nb][3] *= f1;
            }

            // ---- pack P into hi/lo A-fragments ----
            uint32_t aph[4][4], apl[4][4];
            #pragma unroll
            for (int t = 0; t < 4; t++) {
                #pragma unroll
                for (int q = 0; q < 4; q++) {
                    const int blk = 2 * t + (q >> 1);
                    const int e0  = (q & 1) * 2;       // 0 -> c0,c1 ; 1 -> c2,c3
                    float x = sacc[blk][e0], y = sacc[blk][e0 + 1];
                    __nv_bfloat16 hx = __float2bfloat16(x);
                    __nv_bfloat16 hy = __float2bfloat16(y);
                    aph[t][q] = packbf2(hx, hy);
                    apl[t][q] = packbf2(
                        __float2bfloat16(x - __bfloat162float(hx)),
                        __float2bfloat16(y - __bfloat162float(hy)));
                }
            }

            // ---- O += P V (3-term split) ----
            #pragma unroll
            for (int t = 0; t < 4; t++) {
                #pragma unroll
                for (int nb = 0; nb < 8; nb++) {
                    uint32_t vaddr = sbase +
                        (uint32_t)(kvb + 2 * AMAT +
                                   (t * 16 + (lane & 15)) * ASTR + nb * 16 + 8 * (lane >> 4)) * 2;
                    uint32_t vh[4], vl[4];
                    ldsm4t(vh[0], vh[1], vh[2], vh[3], vaddr);
                    ldsm4t(vl[0], vl[1], vl[2], vl[3], vaddr + AMAT * 2);
                    mma16816(oacc[2 * nb],     aph[t], vh[0], vh[1]);
                    mma16816(oacc[2 * nb + 1], aph[t], vh[2], vh[3]);
                    mma16816(oacc[2 * nb],     aph[t], vl[0], vl[1]);
                    mma16816(oacc[2 * nb + 1], aph[t], vl[2], vl[3]);
                    mma16816(oacc[2 * nb],     apl[t], vh[0], vh[1]);
                    mma16816(oacc[2 * nb + 1], apl[t], vh[2], vh[3]);
                }
            }
        }
        __syncthreads();
    }

    // ---- epilogue: normalize, split to hi/lo, store ----
    const float inv0 = 1.f / l0, inv1 = 1.f / l1;
    #pragma unroll
    for (int nb = 0; nb < 16; nb++) {
        const int col = nb * 8 + 2 * (lane & 3);
        float o00 = oacc[nb][0] * inv0, o01 = oacc[nb][1] * inv0;
        float o10 = oacc[nb][2] * inv1, o11 = oacc[nb][3] * inv1;

        size_t i0 = ((size_t)(qrow0 + r) * NH + h) * HD + col;
        size_t i1 = ((size_t)(qrow0 + r + 8) * NH + h) * HD + col;

        __nv_bfloat16 h00 = __float2bfloat16(o00), h01 = __float2bfloat16(o01);
        __nv_bfloat16 h10 = __float2bfloat16(o10), h11 = __float2bfloat16(o11);
        *(uint32_t*)(g_aosplit + i0)        = packbf2(h00, h01);
        *(uint32_t*)(g_aosplit + i1)        = packbf2(h10, h11);
        *(uint32_t*)(g_aosplit + SEGQ + i0) = packbf2(
            __float2bfloat16(o00 - __bfloat162float(h00)),
            __float2bfloat16(o01 - __bfloat162float(h01)));
        *(uint32_t*)(g_aosplit + SEGQ + i1) = packbf2(
            __float2bfloat16(o10 - __bfloat162float(h10)),
            __float2bfloat16(o11 - __bfloat162float(h11)));
    }
}

// ---------------------------------------------------------------------------
// kernel_launch
// ---------------------------------------------------------------------------
extern "C" void kernel_launch(void* const* d_in, const int* in_sizes, int n_in,
                              void* d_out, int out_size)
{
    const float* hidden = (const float*)d_in[0];
    const float* cosp   = (const float*)d_in[1];
    const float* sinp   = (const float*)d_in[2];
    const float* Wq     = (const float*)d_in[3];
    const float* Wk     = (const float*)d_in[4];
    const float* Wv     = (const float*)d_in[5];
    const float* Wo     = (const float*)d_in[6];
    const float* qw     = (const float*)d_in[7];
    const float* kw     = (const float*)d_in[8];
    float* out = (float*)d_out;

    float *qb, *kb, *vb;
    cudaGetSymbolAddress((void**)&qb, g_q);
    cudaGetSymbolAddress((void**)&kb, g_k);
    cudaGetSymbolAddress((void**)&vb, g_v);
    __nv_bfloat16 *hid_h, *hid_l, *wq_h, *wq_l, *wk_h, *wk_l, *wv_h, *wv_l;
    __nv_bfloat16 *wo_h, *wo_l, *kvsp, *aosp;
    cudaGetSymbolAddress((void**)&hid_h, g_hid_h);
    cudaGetSymbolAddress((void**)&hid_l, g_hid_l);
    cudaGetSymbolAddress((void**)&wq_h,  g_wq_h);
    cudaGetSymbolAddress((void**)&wq_l,  g_wq_l);
    cudaGetSymbolAddress((void**)&wk_h,  g_wk_h);
    cudaGetSymbolAddress((void**)&wk_l,  g_wk_l);
    cudaGetSymbolAddress((void**)&wv_h,  g_wv_h);
    cudaGetSymbolAddress((void**)&wv_l,  g_wv_l);
    cudaGetSymbolAddress((void**)&wo_h,  g_wo_h);
    cudaGetSymbolAddress((void**)&wo_l,  g_wo_l);
    cudaGetSymbolAddress((void**)&kvsp,  g_kvsplit);
    cudaGetSymbolAddress((void**)&aosp,  g_aosplit);

    // split conversions for GEMM inputs
    {
        int n;
        n = S_LEN * HID;      cvt_split<<<n / 1024, 256>>>(hidden, hid_h, hid_l, n);
        n = NH * HD * HID;    cvt_split<<<n / 1024, 256>>>(Wq, wq_h, wq_l, n);
        n = NKV * HD * HID;   cvt_split<<<n / 1024, 256>>>(Wk, wk_h, wk_l, n);
        n = NKV * HD * HID;   cvt_split<<<n / 1024, 256>>>(Wv, wv_h, wv_l, n);
        n = HID * NH * HD;    cvt_split<<<n / 1024, 256>>>(Wo, wo_h, wo_l, n);
    }

    const int gemm_smem = 2 * 40960;
    cudaFuncSetAttribute(gemm_bf16split, cudaFuncAttributeMaxDynamicSharedMemorySize, gemm_smem);

    // QKV projections (tensor cores)
    gemm_bf16split<<<dim3(NH * HD / 128,  S_LEN / 128), 256, gemm_smem>>>(
        hid_h, hid_l, wq_h, wq_l, qb, S_LEN, NH * HD,  HID);
    gemm_bf16split<<<dim3(NKV * HD / 128, S_LEN / 128), 256, gemm_smem>>>(
        hid_h, hid_l, wk_h, wk_l, kb, S_LEN, NKV * HD, HID);
    gemm_bf16split<<<dim3(NKV * HD / 128, S_LEN / 128), 256, gemm_smem>>>(
        hid_h, hid_l, wv_h, wv_l, vb, S_LEN, NKV * HD, HID);

    // RMSNorm + RoPE -> bf16 hi/lo splits for attention
    norm_rope_kernel<<<S_LEN * (NH + NKV), 128>>>(cosp, sinp, qw, kw);
    // V -> bf16 hi/lo split
    {
        int n = SEGKV;
        cvt_split<<<n / 1024, 256>>>(vb, kvsp + 2 * (size_t)SEGKV, kvsp + 3 * (size_t)SEGKV, n);
    }

    // tensor-core causal flash attention
    cudaFuncSetAttribute(attn_mma_kernel, cudaFuncAttributeMaxDynamicSharedMemorySize, ATT_SMEM);
    attn_mma_kernel<<<dim3(S_LEN / 128, NH), 256, ATT_SMEM>>>();

    // O projection (tensor cores) -> d_out
    gemm_bf16split<<<dim3(HID / 128, S_LEN / 128), 256, gemm_smem>>>(
        aosp, aosp + (size_t)SEGQ, wo_h, wo_l, out, S_LEN, HID, NH * HD);
}

// round 5
// speedup vs baseline: 5.9993x; 2.1643x over previous
#include <cuda_runtime.h>
#include <cuda_bf16.h>
#include <cuda_fp16.h>
#include <math.h>
#include <stdint.h>

// Problem constants
#define S_LEN 2048
#define HID   4096
#define NH    32
#define NKV   8
#define HD    128
#define ROTD  64
#define RMS_EPS 1e-6f
#define ATT_SCALE 0.08838834764831843f  // 128^-0.5

#define SEGQ  (S_LEN * NH * HD)    // 8388608
#define SEGKV (S_LEN * NKV * HD)   // 2097152

// ---------------------------------------------------------------------------
// Scratch
// ---------------------------------------------------------------------------
__device__ float g_q [S_LEN * NH  * HD];
__device__ float g_k [S_LEN * NKV * HD];
__device__ float g_v [S_LEN * NKV * HD];

// fp16 GEMM operands
__device__ __half g_hid16[S_LEN * HID];
__device__ __half g_wq16 [NH * HD * HID];
__device__ __half g_wk16 [NKV * HD * HID];
__device__ __half g_wv16 [NKV * HD * HID];
__device__ __half g_wo16 [HID * NH * HD];
__device__ __half g_ao16 [S_LEN * NH * HD];

// attention operand splits (bf16 hi/lo, 3-term path)
__device__ __nv_bfloat16 g_qsplit [2 * SEGQ];
__device__ __nv_bfloat16 g_kvsplit[4 * SEGKV];

// ---------------------------------------------------------------------------
// fp32 -> fp16 conversion, 4 elems/thread
// ---------------------------------------------------------------------------
__global__ __launch_bounds__(256) void cvt_f16(
    const float* __restrict__ x, __half* __restrict__ y, int n)
{
    int i = (blockIdx.x * 256 + threadIdx.x) * 4;
    if (i >= n) return;
    float4 v = *(const float4*)(x + i);
    __half h[4] = {__float2half_rn(v.x), __float2half_rn(v.y),
                   __float2half_rn(v.z), __float2half_rn(v.w)};
    *(uint2*)(y + i) = *(uint2*)h;
}

// ---------------------------------------------------------------------------
// fp32 -> (bf16 hi, bf16 lo) split, 4 elems/thread (attention V)
// ---------------------------------------------------------------------------
__global__ __launch_bounds__(256) void cvt_split(
    const float* __restrict__ x, __nv_bfloat16* __restrict__ hi,
    __nv_bfloat16* __restrict__ lo, int n)
{
    int i = (blockIdx.x * 256 + threadIdx.x) * 4;
    if (i >= n) return;
    float4 v = *(const float4*)(x + i);
    __nv_bfloat16 h[4], l[4];
    float vv[4] = {v.x, v.y, v.z, v.w};
    #pragma unroll
    for (int j = 0; j < 4; j++) {
        h[j] = __float2bfloat16(vv[j]);
        l[j] = __float2bfloat16(vv[j] - __bfloat162float(h[j]));
    }
    *(uint2*)(hi + i) = *(uint2*)h;
    *(uint2*)(lo + i) = *(uint2*)l;
}

// ---------------------------------------------------------------------------
// PTX helpers
// ---------------------------------------------------------------------------
__device__ __forceinline__ void cp16(uint32_t s, const void* g) {
    asm volatile("cp.async.cg.shared.global [%0], [%1], 16;\n"
                 :: "r"(s), "l"(g) : "memory");
}
__device__ __forceinline__ void ldsm4(uint32_t& r0, uint32_t& r1,
                                      uint32_t& r2, uint32_t& r3, uint32_t a) {
    asm volatile("ldmatrix.sync.aligned.m8n8.x4.shared.b16 {%0,%1,%2,%3}, [%4];\n"
                 : "=r"(r0), "=r"(r1), "=r"(r2), "=r"(r3) : "r"(a));
}
__device__ __forceinline__ void ldsm4t(uint32_t& r0, uint32_t& r1,
                                       uint32_t& r2, uint32_t& r3, uint32_t a) {
    asm volatile("ldmatrix.sync.aligned.m8n8.x4.trans.shared.b16 {%0,%1,%2,%3}, [%4];\n"
                 : "=r"(r0), "=r"(r1), "=r"(r2), "=r"(r3) : "r"(a));
}
__device__ __forceinline__ void mma16816bf(float* c, const uint32_t* a,
                                           uint32_t b0, uint32_t b1) {
    asm volatile(
        "mma.sync.aligned.m16n8k16.row.col.f32.bf16.bf16.f32 "
        "{%0,%1,%2,%3}, {%4,%5,%6,%7}, {%8,%9}, {%0,%1,%2,%3};\n"
        : "+f"(c[0]), "+f"(c[1]), "+f"(c[2]), "+f"(c[3])
        : "r"(a[0]), "r"(a[1]), "r"(a[2]), "r"(a[3]), "r"(b0), "r"(b1));
}
__device__ __forceinline__ void mma16816h(float* c, const uint32_t* a,
                                          uint32_t b0, uint32_t b1) {
    asm volatile(
        "mma.sync.aligned.m16n8k16.row.col.f32.f16.f16.f32 "
        "{%0,%1,%2,%3}, {%4,%5,%6,%7}, {%8,%9}, {%0,%1,%2,%3};\n"
        : "+f"(c[0]), "+f"(c[1]), "+f"(c[2]), "+f"(c[3])
        : "r"(a[0]), "r"(a[1]), "r"(a[2]), "r"(a[3]), "r"(b0), "r"(b1));
}
__device__ __forceinline__ uint32_t packbf2(__nv_bfloat16 x, __nv_bfloat16 y) {
    __nv_bfloat162 t; t.x = x; t.y = y;
    return *(uint32_t*)&t;
}
__device__ __forceinline__ uint32_t packh2(__half x, __half y) {
    __half2 t; t.x = x; t.y = y;
    return *(uint32_t*)&t;
}

// ---------------------------------------------------------------------------
// fp16 single-term tensor-core GEMM (NT): C[M,N] = A[M,K] @ B[N,K]^T, fp32 acc
// 128x128x64 tiles, 256 threads, 3-stage cp.async, 2 CTAs/SM.
// smem stride 72 halves (144 B rows) -> conflict-free ldmatrix.
// ---------------------------------------------------------------------------
#define FSTR    72
#define FMATB   (128u * FSTR * 2u)       // 18432 B per matrix
#define FSTAGEB (2u * FMATB)             // 36864 B per stage (A + B)
#define FSTAGES 3
#define FSMEM   (FSTAGES * FSTAGEB)      // 110592 B

__global__ void __launch_bounds__(256, 2) gemm_f16(
    const __half* __restrict__ A, const __half* __restrict__ B,
    float* __restrict__ C, int M, int N, int K)
{
    extern __shared__ __half fsm[];
    const uint32_t sbase = (uint32_t)__cvta_generic_to_shared(fsm);
    const int tid  = threadIdx.x;
    const int lane = tid & 31, warp = tid >> 5;
    const int wm = (warp & 3) * 32;
    const int wn = (warp >> 2) * 64;
    const size_t bm = (size_t)blockIdx.y * 128;
    const size_t bn = (size_t)blockIdx.x * 128;
    const int niter = K / 64;

    const int lrow = tid >> 3;        // 0..31  (row group base)
    const int lch  = tid & 7;         // 16B chunk within 64-col row

    auto issue = [&](int it) {
        const int st = it % FSTAGES;
        const uint32_t stb = sbase + (uint32_t)st * FSTAGEB;
        const int k0 = it * 64;
        #pragma unroll
        for (int i = 0; i < 4; i++) {
            const int row = i * 32 + lrow;
            const uint32_t soff = 2u * (uint32_t)(row * FSTR + lch * 8);
            cp16(stb + soff,          A + (bm + row) * K + k0 + lch * 8);
            cp16(stb + FMATB + soff,  B + (bn + row) * K + k0 + lch * 8);
        }
        asm volatile("cp.async.commit_group;\n" ::: "memory");
    };

    float acc[2][8][4];
    #pragma unroll
    for (int i = 0; i < 2; i++)
        #pragma unroll
        for (int j = 0; j < 8; j++)
            #pragma unroll
            for (int k = 0; k < 4; k++) acc[i][j][k] = 0.f;

    issue(0);
    if (niter > 1) issue(1);
    if (niter > 2) issue(2);

    const int a_r = lane & 15;
    const int b_r = (lane & 7) + ((lane >> 3) & 1) * 8;
    const int khl = (lane >> 4) * 8;

    for (int it = 0; it < niter; ++it) {
        const int rem = niter - 1 - it;
        if (rem >= 2)      asm volatile("cp.async.wait_group 2;\n" ::: "memory");
        else if (rem == 1) asm volatile("cp.async.wait_group 1;\n" ::: "memory");
        else               asm volatile("cp.async.wait_group 0;\n" ::: "memory");
        __syncthreads();

        const uint32_t sb = sbase + (uint32_t)(it % FSTAGES) * FSTAGEB;
        #pragma unroll
        for (int kk = 0; kk < 64; kk += 16) {
            uint32_t a[2][4];
            #pragma unroll
            for (int mb = 0; mb < 2; mb++) {
                uint32_t addr = sb + 2u * (uint32_t)((wm + mb * 16 + a_r) * FSTR + kk + khl);
                ldsm4(a[mb][0], a[mb][1], a[mb][2], a[mb][3], addr);
            }
            uint32_t b[4][4];
            #pragma unroll
            for (int nb = 0; nb < 4; nb++) {
                uint32_t addr = sb + FMATB +
                    2u * (uint32_t)((wn + nb * 16 + b_r) * FSTR + kk + khl);
                ldsm4(b[nb][0], b[nb][1], b[nb][2], b[nb][3], addr);
            }
            #pragma unroll
            for (int mb = 0; mb < 2; mb++) {
                #pragma unroll
                for (int n8 = 0; n8 < 8; n8++) {
                    const int nb = n8 >> 1, ww = n8 & 1;
                    mma16816h(acc[mb][n8], a[mb], b[nb][ww], b[nb][ww + 2]);
                }
            }
        }
        __syncthreads();
        if (it + FSTAGES < niter) issue(it + FSTAGES);
    }

    #pragma unroll
    for (int mb = 0; mb < 2; mb++) {
        const size_t row = bm + wm + mb * 16 + (lane >> 2);
        #pragma unroll
        for (int n8 = 0; n8 < 8; n8++) {
            const size_t col = bn + wn + n8 * 8 + (lane & 3) * 2;
            *(float2*)&C[row * N + col] = make_float2(acc[mb][n8][0], acc[mb][n8][1]);
            *(float2*)&C[(row + 8) * N + col] = make_float2(acc[mb][n8][2], acc[mb][n8][3]);
        }
    }
}

// ---------------------------------------------------------------------------
// Fused per-head RMSNorm + partial RoPE: reads fp32 q/k, writes bf16 hi/lo
// ---------------------------------------------------------------------------
__global__ __launch_bounds__(128) void norm_rope_kernel(
    const float* __restrict__ cosp, const float* __restrict__ sinp,
    const float* __restrict__ qw,   const float* __restrict__ kw)
{
    const int bid = blockIdx.x;
    const int d = threadIdx.x;
    const int lane = d & 31, wid = d >> 5;

    const float* base;
    __nv_bfloat16 *dst_h, *dst_l;
    int s_idx;
    const float* w;
    size_t idx;
    if (bid < S_LEN * NH) {
        s_idx = bid / NH;
        idx   = (size_t)bid * HD + d;
        base  = g_q + (size_t)bid * HD;
        dst_h = g_qsplit;  dst_l = g_qsplit + SEGQ;
        w     = qw;
    } else {
        int b2 = bid - S_LEN * NH;
        s_idx = b2 / NKV;
        idx   = (size_t)b2 * HD + d;
        base  = g_k + (size_t)b2 * HD;
        dst_h = g_kvsplit; dst_l = g_kvsplit + SEGKV;
        w     = kw;
    }

    float x = base[d];
    float v = x * x;
    #pragma unroll
    for (int o = 16; o > 0; o >>= 1) v += __shfl_xor_sync(0xffffffffu, v, o);
    __shared__ float red[4];
    __shared__ float xb[128];
    if (lane == 0) red[wid] = v;
    __syncthreads();
    float sum = red[0] + red[1] + red[2] + red[3];
    float rs = rsqrtf(sum * (1.0f / HD) + RMS_EPS);

    float xn = x * rs * w[d];
    xb[d] = xn;
    __syncthreads();

    float out;
    if (d < ROTD) {
        float c  = cosp[(size_t)s_idx * ROTD + d];
        float sn = sinp[(size_t)s_idx * ROTD + d];
        float partner = (d < 32) ? -xb[d + 32] : xb[d - 32];
        out = xn * c + partner * sn;
    } else {
        out = xn;
    }
    __nv_bfloat16 h = __float2bfloat16(out);
    dst_h[idx] = h;
    dst_l[idx] = __float2bfloat16(out - __bfloat162float(h));
}

// ---------------------------------------------------------------------------
// Tensor-core causal flash attention (bf16 hi/lo split, 3-term).
// Epilogue writes fp16 (for O-projection).
// ---------------------------------------------------------------------------
#define ASTR 136
#define QMAT (128 * ASTR)
#define AMAT (64 * ASTR)
#define ATT_SMEM ((2 * QMAT + 8 * AMAT) * 2)

__global__ __launch_bounds__(256) void attn_mma_kernel()
{
    extern __shared__ __nv_bfloat16 sh[];
    const uint32_t sbase = (uint32_t)__cvta_generic_to_shared(sh);

    const int tid  = threadIdx.x;
    const int lane = tid & 31, w = tid >> 5;
    const int qtile = (S_LEN / 128 - 1) - blockIdx.x;
    const int h  = blockIdx.y;
    const int hk = h >> 2;
    const int q0 = qtile * 128;
    const int qrow0 = q0 + w * 16;
    const int jmax = 2 * qtile + 1;

    const int b_r = (lane & 7) + ((lane >> 3) & 1) * 8;
    const int khl = (lane >> 4) * 8;
    const int r   = lane >> 2;

    auto load_q = [&]() {
        #pragma unroll
        for (int i = 0; i < 16; i++) {
            int c   = tid + i * 256;
            int mat = c >> 11;
            int rem = c & 2047;
            int row = rem >> 4, col = rem & 15;
            const __nv_bfloat16* src = g_qsplit + (size_t)mat * SEGQ +
                ((size_t)(q0 + row) * NH + h) * HD + col * 8;
            uint32_t dst = sbase + (uint32_t)(mat * QMAT + row * ASTR) * 2 + col * 16;
            cp16(dst, src);
        }
    };
    auto load_kv = [&](int j) {
        const int kvb = 2 * QMAT + (j & 1) * 4 * AMAT;
        #pragma unroll
        for (int i = 0; i < 16; i++) {
            int c   = tid + i * 256;
            int mat = c >> 10;
            int rem = c & 1023;
            int row = rem >> 4, col = rem & 15;
            const __nv_bfloat16* src = g_kvsplit + (size_t)mat * SEGKV +
                ((size_t)(j * 64 + row) * NKV + hk) * HD + col * 8;
            uint32_t dst = sbase + (uint32_t)(kvb + mat * AMAT + row * ASTR) * 2 + col * 16;
            cp16(dst, src);
        }
    };

    load_q();
    load_kv(0);
    asm volatile("cp.async.commit_group;\n" ::: "memory");

    float oacc[16][4];
    #pragma unroll
    for (int i = 0; i < 16; i++)
        #pragma unroll
        for (int e = 0; e < 4; e++) oacc[i][e] = 0.f;
    float m0 = -INFINITY, m1 = -INFINITY, l0 = 0.f, l1 = 0.f;

    for (int j = 0; j <= jmax; j++) {
        const bool ahead = (j + 1 <= jmax);
        if (ahead) {
            load_kv(j + 1);
            asm volatile("cp.async.commit_group;\n" ::: "memory");
            asm volatile("cp.async.wait_group 1;\n" ::: "memory");
        } else {
            asm volatile("cp.async.wait_group 0;\n" ::: "memory");
        }
        __syncthreads();

        const bool active = (j * 64 <= qrow0 + 15);
        if (active) {
            const int kvb = 2 * QMAT + (j & 1) * 4 * AMAT;

            float sacc[8][4];
            #pragma unroll
            for (int b = 0; b < 8; b++)
                #pragma unroll
                for (int e = 0; e < 4; e++) sacc[b][e] = 0.f;

            #pragma unroll
            for (int k0 = 0; k0 < 8; k0++) {
                uint32_t qaddr = sbase +
                    (uint32_t)((w * 16 + (lane & 15)) * ASTR + k0 * 16 + 8 * (lane >> 4)) * 2;
                uint32_t aqh[4], aql[4];
                ldsm4(aqh[0], aqh[1], aqh[2], aqh[3], qaddr);
                ldsm4(aql[0], aql[1], aql[2], aql[3], qaddr + QMAT * 2);
                #pragma unroll
                for (int nb = 0; nb < 4; nb++) {
                    uint32_t kaddr = sbase +
                        (uint32_t)(kvb + (nb * 16 + b_r) * ASTR + k0 * 16 + khl) * 2;
                    uint32_t kh[4], kl[4];
                    ldsm4(kh[0], kh[1], kh[2], kh[3], kaddr);
                    ldsm4(kl[0], kl[1], kl[2], kl[3], kaddr + AMAT * 2);
                    mma16816bf(sacc[2 * nb],     aqh, kh[0], kh[2]);
                    mma16816bf(sacc[2 * nb + 1], aqh, kh[1], kh[3]);
                    mma16816bf(sacc[2 * nb],     aqh, kl[0], kl[2]);
                    mma16816bf(sacc[2 * nb + 1], aqh, kl[1], kl[3]);
                    mma16816bf(sacc[2 * nb],     aql, kh[0], kh[2]);
                    mma16816bf(sacc[2 * nb + 1], aql, kh[1], kh[3]);
                }
            }

            const bool full = (j * 64 + 63 <= qrow0);
            #pragma unroll
            for (int b = 0; b < 8; b++)
                #pragma unroll
                for (int e = 0; e < 4; e++) sacc[b][e] *= ATT_SCALE;
            if (!full) {
                #pragma unroll
                for (int b = 0; b < 8; b++) {
                    int colb = j * 64 + b * 8 + 2 * (lane & 3);
                    int rlo = qrow0 + r, rhi = rlo + 8;
                    if (colb     > rlo) sacc[b][0] = -1e30f;
                    if (colb + 1 > rlo) sacc[b][1] = -1e30f;
                    if (colb     > rhi) sacc[b][2] = -1e30f;
                    if (colb + 1 > rhi) sacc[b][3] = -1e30f;
                }
            }

            float mx0 = -INFINITY, mx1 = -INFINITY;
            #pragma unroll
            for (int b = 0; b < 8; b++) {
                mx0 = fmaxf(mx0, fmaxf(sacc[b][0], sacc[b][1]));
                mx1 = fmaxf(mx1, fmaxf(sacc[b][2], sacc[b][3]));
            }
            mx0 = fmaxf(mx0, __shfl_xor_sync(0xffffffffu, mx0, 1));
            mx0 = fmaxf(mx0, __shfl_xor_sync(0xffffffffu, mx0, 2));
            mx1 = fmaxf(mx1, __shfl_xor_sync(0xffffffffu, mx1, 1));
            mx1 = fmaxf(mx1, __shfl_xor_sync(0xffffffffu, mx1, 2));
            float mn0 = fmaxf(m0, mx0), mn1 = fmaxf(m1, mx1);
            float f0 = __expf(m0 - mn0), f1 = __expf(m1 - mn1);
            m0 = mn0; m1 = mn1;

            float s0 = 0.f, s1 = 0.f;
            #pragma unroll
            for (int b = 0; b < 8; b++) {
                sacc[b][0] = __expf(sacc[b][0] - mn0);
                sacc[b][1] = __expf(sacc[b][1] - mn0);
                sacc[b][2] = __expf(sacc[b][2] - mn1);
                sacc[b][3] = __expf(sacc[b][3] - mn1);
                s0 += sacc[b][0] + sacc[b][1];
                s1 += sacc[b][2] + sacc[b][3];
            }
            s0 += __shfl_xor_sync(0xffffffffu, s0, 1);
            s0 += __shfl_xor_sync(0xffffffffu, s0, 2);
            s1 += __shfl_xor_sync(0xffffffffu, s1, 1);
            s1 += __shfl_xor_sync(0xffffffffu, s1, 2);
            l0 = l0 * f0 + s0;
            l1 = l1 * f1 + s1;

            #pragma unroll
            for (int nb = 0; nb < 16; nb++) {
                oacc[nb][0] *= f0; oacc[nb][1] *= f0;
                oacc[nb][2] *= f1; oacc[nb][3] *= f1;
            }

            uint32_t aph[4][4], apl[4][4];
            #pragma unroll
            for (int t = 0; t < 4; t++) {
                #pragma unroll
                for (int q = 0; q < 4; q++) {
                    const int blk = 2 * t + (q >> 1);
                    const int e0  = (q & 1) * 2;
                    float x = sacc[blk][e0], y = sacc[blk][e0 + 1];
                    __nv_bfloat16 hx = __float2bfloat16(x);
                    __nv_bfloat16 hy = __float2bfloat16(y);
                    aph[t][q] = packbf2(hx, hy);
                    apl[t][q] = packbf2(
                        __float2bfloat16(x - __bfloat162float(hx)),
                        __float2bfloat16(y - __bfloat162float(hy)));
                }
            }

            #pragma unroll
            for (int t = 0; t < 4; t++) {
                #pragma unroll
                for (int nb = 0; nb < 8; nb++) {
                    uint32_t vaddr = sbase +
                        (uint32_t)(kvb + 2 * AMAT +
                                   (t * 16 + (lane & 15)) * ASTR + nb * 16 + 8 * (lane >> 4)) * 2;
                    uint32_t vh[4], vl[4];
                    ldsm4t(vh[0], vh[1], vh[2], vh[3], vaddr);
                    ldsm4t(vl[0], vl[1], vl[2], vl[3], vaddr + AMAT * 2);
                    mma16816bf(oacc[2 * nb],     aph[t], vh[0], vh[1]);
                    mma16816bf(oacc[2 * nb + 1], aph[t], vh[2], vh[3]);
                    mma16816bf(oacc[2 * nb],     aph[t], vl[0], vl[1]);
                    mma16816bf(oacc[2 * nb + 1], aph[t], vl[2], vl[3]);
                    mma16816bf(oacc[2 * nb],     apl[t], vh[0], vh[1]);
                    mma16816bf(oacc[2 * nb + 1], apl[t], vh[2], vh[3]);
                }
            }
        }
        __syncthreads();
    }

    // epilogue: normalize, write fp16 for O projection
    const float inv0 = 1.f / l0, inv1 = 1.f / l1;
    #pragma unroll
    for (int nb = 0; nb < 16; nb++) {
        const int col = nb * 8 + 2 * (lane & 3);
        float o00 = oacc[nb][0] * inv0, o01 = oacc[nb][1] * inv0;
        float o10 = oacc[nb][2] * inv1, o11 = oacc[nb][3] * inv1;

        size_t i0 = ((size_t)(qrow0 + r) * NH + h) * HD + col;
        size_t i1 = ((size_t)(qrow0 + r + 8) * NH + h) * HD + col;

        *(uint32_t*)(g_ao16 + i0) = packh2(__float2half_rn(o00), __float2half_rn(o01));
        *(uint32_t*)(g_ao16 + i1) = packh2(__float2half_rn(o10), __float2half_rn(o11));
    }
}

// ---------------------------------------------------------------------------
// kernel_launch
// ---------------------------------------------------------------------------
extern "C" void kernel_launch(void* const* d_in, const int* in_sizes, int n_in,
                              void* d_out, int out_size)
{
    const float* hidden = (const float*)d_in[0];
    const float* cosp   = (const float*)d_in[1];
    const float* sinp   = (const float*)d_in[2];
    const float* Wq     = (const float*)d_in[3];
    const float* Wk     = (const float*)d_in[4];
    const float* Wv     = (const float*)d_in[5];
    const float* Wo     = (const float*)d_in[6];
    const float* qw     = (const float*)d_in[7];
    const float* kw     = (const float*)d_in[8];
    float* out = (float*)d_out;

    float *qb, *kb, *vb;
    cudaGetSymbolAddress((void**)&qb, g_q);
    cudaGetSymbolAddress((void**)&kb, g_k);
    cudaGetSymbolAddress((void**)&vb, g_v);
    __half *hid16, *wq16, *wk16, *wv16, *wo16, *ao16;
    __nv_bfloat16 *kvsp;
    cudaGetSymbolAddress((void**)&hid16, g_hid16);
    cudaGetSymbolAddress((void**)&wq16,  g_wq16);
    cudaGetSymbolAddress((void**)&wk16,  g_wk16);
    cudaGetSymbolAddress((void**)&wv16,  g_wv16);
    cudaGetSymbolAddress((void**)&wo16,  g_wo16);
    cudaGetSymbolAddress((void**)&ao16,  g_ao16);
    cudaGetSymbolAddress((void**)&kvsp,  g_kvsplit);

    // fp16 conversions
    {
        int n;
        n = S_LEN * HID;      cvt_f16<<<n / 1024, 256>>>(hidden, hid16, n);
        n = NH * HD * HID;    cvt_f16<<<n / 1024, 256>>>(Wq, wq16, n);
        n = NKV * HD * HID;   cvt_f16<<<n / 1024, 256>>>(Wk, wk16, n);
        n = NKV * HD * HID;   cvt_f16<<<n / 1024, 256>>>(Wv, wv16, n);
        n = HID * NH * HD;    cvt_f16<<<n / 1024, 256>>>(Wo, wo16, n);
    }

    cudaFuncSetAttribute(gemm_f16, cudaFuncAttributeMaxDynamicSharedMemorySize, FSMEM);

    // QKV projections (fp16 single-term HMMA)
    gemm_f16<<<dim3(NH * HD / 128,  S_LEN / 128), 256, FSMEM>>>(
        hid16, wq16, qb, S_LEN, NH * HD,  HID);
    gemm_f16<<<dim3(NKV * HD / 128, S_LEN / 128), 256, FSMEM>>>(
        hid16, wk16, kb, S_LEN, NKV * HD, HID);
    gemm_f16<<<dim3(NKV * HD / 128, S_LEN / 128), 256, FSMEM>>>(
        hid16, wv16, vb, S_LEN, NKV * HD, HID);

    // RMSNorm + RoPE -> bf16 hi/lo splits for attention
    norm_rope_kernel<<<S_LEN * (NH + NKV), 128>>>(cosp, sinp, qw, kw);
    // V -> bf16 hi/lo split
    {
        int n = SEGKV;
        cvt_split<<<n / 1024, 256>>>(vb, kvsp + 2 * (size_t)SEGKV, kvsp + 3 * (size_t)SEGKV, n);
    }

    // tensor-core causal flash attention (bf16 3-term) -> fp16 ao
    cudaFuncSetAttribute(attn_mma_kernel, cudaFuncAttributeMaxDynamicSharedMemorySize, ATT_SMEM);
    attn_mma_kernel<<<dim3(S_LEN / 128, NH), 256, ATT_SMEM>>>();

    // O projection (fp16 single-term HMMA) -> d_out
    gemm_f16<<<dim3(HID / 128, S_LEN / 128), 256, FSMEM>>>(
        ao16, wo16, out, S_LEN, HID, NH * HD);
}

// round 6
// speedup vs baseline: 7.3804x; 1.2302x over previous
#include <cuda_runtime.h>
#include <cuda_bf16.h>
#include <cuda_fp16.h>
#include <math.h>
#include <stdint.h>

// Problem constants
#define S_LEN 2048
#define HID   4096
#define NH    32
#define NKV   8
#define HD    128
#define ROTD  64
#define RMS_EPS 1e-6f
#define ATT_SCALE 0.08838834764831843f  // 128^-0.5

#define SEGQ  (S_LEN * NH * HD)    // 8388608
#define SEGKV (S_LEN * NKV * HD)   // 2097152

// ---------------------------------------------------------------------------
// Scratch
// ---------------------------------------------------------------------------
__device__ float g_q [S_LEN * NH  * HD];   // fp32 Q pre-norm
__device__ float g_k [S_LEN * NKV * HD];   // fp32 K pre-norm

__device__ __half g_hid16[S_LEN * HID];
__device__ __half g_wq16 [NH * HD * HID];
__device__ __half g_wk16 [NKV * HD * HID];
__device__ __half g_wv16 [NKV * HD * HID];
__device__ __half g_wo16 [HID * NH * HD];

__device__ __half g_q16 [SEGQ];    // post norm+rope Q (fp16)
__device__ __half g_k16 [SEGKV];   // post norm+rope K (fp16)
__device__ __half g_v16 [SEGKV];   // V (fp16, direct from GEMM)
__device__ __half g_ao16[SEGQ];    // attention out (fp16)

// ---------------------------------------------------------------------------
// fp32 -> fp16 conversion, 4 elems/thread
// ---------------------------------------------------------------------------
__global__ __launch_bounds__(256) void cvt_f16(
    const float* __restrict__ x, __half* __restrict__ y, int n)
{
    int i = (blockIdx.x * 256 + threadIdx.x) * 4;
    if (i >= n) return;
    float4 v = *(const float4*)(x + i);
    __half h[4] = {__float2half_rn(v.x), __float2half_rn(v.y),
                   __float2half_rn(v.z), __float2half_rn(v.w)};
    *(uint2*)(y + i) = *(uint2*)h;
}

// ---------------------------------------------------------------------------
// PTX helpers
// ---------------------------------------------------------------------------
__device__ __forceinline__ void cp16(uint32_t s, const void* g) {
    asm volatile("cp.async.cg.shared.global [%0], [%1], 16;\n"
                 :: "r"(s), "l"(g) : "memory");
}
__device__ __forceinline__ void ldsm4(uint32_t& r0, uint32_t& r1,
                                      uint32_t& r2, uint32_t& r3, uint32_t a) {
    asm volatile("ldmatrix.sync.aligned.m8n8.x4.shared.b16 {%0,%1,%2,%3}, [%4];\n"
                 : "=r"(r0), "=r"(r1), "=r"(r2), "=r"(r3) : "r"(a));
}
__device__ __forceinline__ void ldsm4t(uint32_t& r0, uint32_t& r1,
                                       uint32_t& r2, uint32_t& r3, uint32_t a) {
    asm volatile("ldmatrix.sync.aligned.m8n8.x4.trans.shared.b16 {%0,%1,%2,%3}, [%4];\n"
                 : "=r"(r0), "=r"(r1), "=r"(r2), "=r"(r3) : "r"(a));
}
__device__ __forceinline__ void mma16816h(float* c, const uint32_t* a,
                                          uint32_t b0, uint32_t b1) {
    asm volatile(
        "mma.sync.aligned.m16n8k16.row.col.f32.f16.f16.f32 "
        "{%0,%1,%2,%3}, {%4,%5,%6,%7}, {%8,%9}, {%0,%1,%2,%3};\n"
        : "+f"(c[0]), "+f"(c[1]), "+f"(c[2]), "+f"(c[3])
        : "r"(a[0]), "r"(a[1]), "r"(a[2]), "r"(a[3]), "r"(b0), "r"(b1));
}
__device__ __forceinline__ uint32_t packh2(__half x, __half y) {
    __half2 t; t.x = x; t.y = y;
    return *(uint32_t*)&t;
}

// ---------------------------------------------------------------------------
// fp16 tensor-core GEMM (NT): C[M,N] = A[M,K] @ B[N,K]^T, fp32 acc.
// 128x128x64 tiles, 256 threads, 3-stage cp.async, 2 CTAs/SM.
// Templated output: float or __half.
// ---------------------------------------------------------------------------
#define FSTR    72
#define FMATB   (128u * FSTR * 2u)       // 18432 B per matrix
#define FSTAGEB (2u * FMATB)             // 36864 B per stage
#define FSTAGES 3
#define FSMEM   (FSTAGES * FSTAGEB)      // 110592 B

template <typename OutT>
__global__ void __launch_bounds__(256, 2) gemm_f16(
    const __half* __restrict__ A, const __half* __restrict__ B,
    OutT* __restrict__ C, int M, int N, int K)
{
    extern __shared__ __half fsm[];
    const uint32_t sbase = (uint32_t)__cvta_generic_to_shared(fsm);
    const int tid  = threadIdx.x;
    const int lane = tid & 31, warp = tid >> 5;
    const int wm = (warp & 3) * 32;
    const int wn = (warp >> 2) * 64;
    const size_t bm = (size_t)blockIdx.y * 128;
    const size_t bn = (size_t)blockIdx.x * 128;
    const int niter = K / 64;

    const int lrow = tid >> 3;
    const int lch  = tid & 7;

    auto issue = [&](int it) {
        const int st = it % FSTAGES;
        const uint32_t stb = sbase + (uint32_t)st * FSTAGEB;
        const int k0 = it * 64;
        #pragma unroll
        for (int i = 0; i < 4; i++) {
            const int row = i * 32 + lrow;
            const uint32_t soff = 2u * (uint32_t)(row * FSTR + lch * 8);
            cp16(stb + soff,          A + (bm + row) * K + k0 + lch * 8);
            cp16(stb + FMATB + soff,  B + (bn + row) * K + k0 + lch * 8);
        }
        asm volatile("cp.async.commit_group;\n" ::: "memory");
    };

    float acc[2][8][4];
    #pragma unroll
    for (int i = 0; i < 2; i++)
        #pragma unroll
        for (int j = 0; j < 8; j++)
            #pragma unroll
            for (int k = 0; k < 4; k++) acc[i][j][k] = 0.f;

    issue(0);
    if (niter > 1) issue(1);
    if (niter > 2) issue(2);

    const int a_r = lane & 15;
    const int b_r = (lane & 7) + ((lane >> 3) & 1) * 8;
    const int khl = (lane >> 4) * 8;

    for (int it = 0; it < niter; ++it) {
        const int rem = niter - 1 - it;
        if (rem >= 2)      asm volatile("cp.async.wait_group 2;\n" ::: "memory");
        else if (rem == 1) asm volatile("cp.async.wait_group 1;\n" ::: "memory");
        else               asm volatile("cp.async.wait_group 0;\n" ::: "memory");
        __syncthreads();

        const uint32_t sb = sbase + (uint32_t)(it % FSTAGES) * FSTAGEB;
        #pragma unroll
        for (int kk = 0; kk < 64; kk += 16) {
            uint32_t a[2][4];
            #pragma unroll
            for (int mb = 0; mb < 2; mb++) {
                uint32_t addr = sb + 2u * (uint32_t)((wm + mb * 16 + a_r) * FSTR + kk + khl);
                ldsm4(a[mb][0], a[mb][1], a[mb][2], a[mb][3], addr);
            }
            uint32_t b[4][4];
            #pragma unroll
            for (int nb = 0; nb < 4; nb++) {
                uint32_t addr = sb + FMATB +
                    2u * (uint32_t)((wn + nb * 16 + b_r) * FSTR + kk + khl);
                ldsm4(b[nb][0], b[nb][1], b[nb][2], b[nb][3], addr);
            }
            #pragma unroll
            for (int mb = 0; mb < 2; mb++) {
                #pragma unroll
                for (int n8 = 0; n8 < 8; n8++) {
                    const int nb = n8 >> 1, ww = n8 & 1;
                    mma16816h(acc[mb][n8], a[mb], b[nb][ww], b[nb][ww + 2]);
                }
            }
        }
        __syncthreads();
        if (it + FSTAGES < niter) issue(it + FSTAGES);
    }

    #pragma unroll
    for (int mb = 0; mb < 2; mb++) {
        const size_t row = bm + wm + mb * 16 + (lane >> 2);
        #pragma unroll
        for (int n8 = 0; n8 < 8; n8++) {
            const size_t col = bn + wn + n8 * 8 + (lane & 3) * 2;
            if constexpr (sizeof(OutT) == 4) {
                *(float2*)&C[row * N + col] = make_float2(acc[mb][n8][0], acc[mb][n8][1]);
                *(float2*)&C[(row + 8) * N + col] = make_float2(acc[mb][n8][2], acc[mb][n8][3]);
            } else {
                *(uint32_t*)&C[row * N + col] =
                    packh2(__float2half_rn(acc[mb][n8][0]), __float2half_rn(acc[mb][n8][1]));
                *(uint32_t*)&C[(row + 8) * N + col] =
                    packh2(__float2half_rn(acc[mb][n8][2]), __float2half_rn(acc[mb][n8][3]));
            }
        }
    }
}

// ---------------------------------------------------------------------------
// Fused per-head RMSNorm + partial RoPE: reads fp32 q/k, writes fp16
// ---------------------------------------------------------------------------
__global__ __launch_bounds__(128) void norm_rope_kernel(
    const float* __restrict__ cosp, const float* __restrict__ sinp,
    const float* __restrict__ qw,   const float* __restrict__ kw)
{
    const int bid = blockIdx.x;
    const int d = threadIdx.x;
    const int lane = d & 31, wid = d >> 5;

    const float* base;
    __half* dst;
    int s_idx;
    const float* w;
    size_t idx;
    if (bid < S_LEN * NH) {
        s_idx = bid / NH;
        idx   = (size_t)bid * HD + d;
        base  = g_q + (size_t)bid * HD;
        dst   = g_q16;
        w     = qw;
    } else {
        int b2 = bid - S_LEN * NH;
        s_idx = b2 / NKV;
        idx   = (size_t)b2 * HD + d;
        base  = g_k + (size_t)b2 * HD;
        dst   = g_k16;
        w     = kw;
    }

    float x = base[d];
    float v = x * x;
    #pragma unroll
    for (int o = 16; o > 0; o >>= 1) v += __shfl_xor_sync(0xffffffffu, v, o);
    __shared__ float red[4];
    __shared__ float xb[128];
    if (lane == 0) red[wid] = v;
    __syncthreads();
    float sum = red[0] + red[1] + red[2] + red[3];
    float rs = rsqrtf(sum * (1.0f / HD) + RMS_EPS);

    float xn = x * rs * w[d];
    xb[d] = xn;
    __syncthreads();

    float out;
    if (d < ROTD) {
        float c  = cosp[(size_t)s_idx * ROTD + d];
        float sn = sinp[(size_t)s_idx * ROTD + d];
        float partner = (d < 32) ? -xb[d + 32] : xb[d - 32];
        out = xn * c + partner * sn;
    } else {
        out = xn;
    }
    dst[idx] = __float2half_rn(out);
}

// ---------------------------------------------------------------------------
// fp16 tensor-core causal flash attention.
// BM=128 (8 warps x 16 rows), BN=64, D=128, 256 threads, 2 CTAs/SM.
// smem: Q [128][136] + double-buffered K,V [64][136] fp16 = 104448 B.
// ---------------------------------------------------------------------------
#define ASTR 136
#define QMAT (128 * ASTR)
#define AMAT (64 * ASTR)
#define ATT_SMEM ((QMAT + 4 * AMAT) * 2)   // 104448 B

__global__ void __launch_bounds__(256, 2) attn_mma_kernel()
{
    extern __shared__ __half sh[];
    const uint32_t sbase = (uint32_t)__cvta_generic_to_shared(sh);

    const int tid  = threadIdx.x;
    const int lane = tid & 31, w = tid >> 5;
    const int qtile = (S_LEN / 128 - 1) - blockIdx.x;   // largest first
    const int h  = blockIdx.y;
    const int hk = h >> 2;
    const int q0 = qtile * 128;
    const int qrow0 = q0 + w * 16;
    const int jmax = 2 * qtile + 1;

    const int b_r = (lane & 7) + ((lane >> 3) & 1) * 8;
    const int khl = (lane >> 4) * 8;
    const int r   = lane >> 2;

    auto load_q = [&]() {
        #pragma unroll
        for (int i = 0; i < 8; i++) {
            int c   = tid + i * 256;          // 0..2047
            int row = c >> 4, col = c & 15;
            const __half* src = g_q16 + ((size_t)(q0 + row) * NH + h) * HD + col * 8;
            uint32_t dst = sbase + (uint32_t)(row * ASTR) * 2 + col * 16;
            cp16(dst, src);
        }
    };
    auto load_kv = [&](int j) {
        const int kvb = QMAT + (j & 1) * 2 * AMAT;
        #pragma unroll
        for (int i = 0; i < 8; i++) {
            int c   = tid + i * 256;          // 0..2047
            int mat = c >> 10;                // 0:K 1:V
            int rem = c & 1023;
            int row = rem >> 4, col = rem & 15;
            const __half* srcb = (mat == 0) ? g_k16 : g_v16;
            const __half* src = srcb + ((size_t)(j * 64 + row) * NKV + hk) * HD + col * 8;
            uint32_t dst = sbase + (uint32_t)(kvb + mat * AMAT + row * ASTR) * 2 + col * 16;
            cp16(dst, src);
        }
    };

    load_q();
    load_kv(0);
    asm volatile("cp.async.commit_group;\n" ::: "memory");

    float oacc[16][4];
    #pragma unroll
    for (int i = 0; i < 16; i++)
        #pragma unroll
        for (int e = 0; e < 4; e++) oacc[i][e] = 0.f;
    float m0 = -INFINITY, m1 = -INFINITY, l0 = 0.f, l1 = 0.f;

    for (int j = 0; j <= jmax; j++) {
        const bool ahead = (j + 1 <= jmax);
        if (ahead) {
            load_kv(j + 1);
            asm volatile("cp.async.commit_group;\n" ::: "memory");
            asm volatile("cp.async.wait_group 1;\n" ::: "memory");
        } else {
            asm volatile("cp.async.wait_group 0;\n" ::: "memory");
        }
        __syncthreads();

        const bool active = (j * 64 <= qrow0 + 15);
        if (active) {
            const int kvb = QMAT + (j & 1) * 2 * AMAT;

            // ---- S = Q K^T (fp16 single-term) ----
            float sacc[8][4];
            #pragma unroll
            for (int b = 0; b < 8; b++)
                #pragma unroll
                for (int e = 0; e < 4; e++) sacc[b][e] = 0.f;

            #pragma unroll
            for (int k0 = 0; k0 < 8; k0++) {
                uint32_t qaddr = sbase +
                    (uint32_t)((w * 16 + (lane & 15)) * ASTR + k0 * 16 + 8 * (lane >> 4)) * 2;
                uint32_t aq[4];
                ldsm4(aq[0], aq[1], aq[2], aq[3], qaddr);
                #pragma unroll
                for (int nb = 0; nb < 4; nb++) {
                    uint32_t kaddr = sbase +
                        (uint32_t)(kvb + (nb * 16 + b_r) * ASTR + k0 * 16 + khl) * 2;
                    uint32_t kf[4];
                    ldsm4(kf[0], kf[1], kf[2], kf[3], kaddr);
                    mma16816h(sacc[2 * nb],     aq, kf[0], kf[2]);
                    mma16816h(sacc[2 * nb + 1], aq, kf[1], kf[3]);
                }
            }

            // ---- scale + causal mask ----
            const bool full = (j * 64 + 63 <= qrow0);
            #pragma unroll
            for (int b = 0; b < 8; b++)
                #pragma unroll
                for (int e = 0; e < 4; e++) sacc[b][e] *= ATT_SCALE;
            if (!full) {
                #pragma unroll
                for (int b = 0; b < 8; b++) {
                    int colb = j * 64 + b * 8 + 2 * (lane & 3);
                    int rlo = qrow0 + r, rhi = rlo + 8;
                    if (colb     > rlo) sacc[b][0] = -1e30f;
                    if (colb + 1 > rlo) sacc[b][1] = -1e30f;
                    if (colb     > rhi) sacc[b][2] = -1e30f;
                    if (colb + 1 > rhi) sacc[b][3] = -1e30f;
                }
            }

            // ---- online softmax ----
            float mx0 = -INFINITY, mx1 = -INFINITY;
            #pragma unroll
            for (int b = 0; b < 8; b++) {
                mx0 = fmaxf(mx0, fmaxf(sacc[b][0], sacc[b][1]));
                mx1 = fmaxf(mx1, fmaxf(sacc[b][2], sacc[b][3]));
            }
            mx0 = fmaxf(mx0, __shfl_xor_sync(0xffffffffu, mx0, 1));
            mx0 = fmaxf(mx0, __shfl_xor_sync(0xffffffffu, mx0, 2));
            mx1 = fmaxf(mx1, __shfl_xor_sync(0xffffffffu, mx1, 1));
            mx1 = fmaxf(mx1, __shfl_xor_sync(0xffffffffu, mx1, 2));
            float mn0 = fmaxf(m0, mx0), mn1 = fmaxf(m1, mx1);
            float f0 = __expf(m0 - mn0), f1 = __expf(m1 - mn1);
            m0 = mn0; m1 = mn1;

            float s0 = 0.f, s1 = 0.f;
            #pragma unroll
            for (int b = 0; b < 8; b++) {
                sacc[b][0] = __expf(sacc[b][0] - mn0);
                sacc[b][1] = __expf(sacc[b][1] - mn0);
                sacc[b][2] = __expf(sacc[b][2] - mn1);
                sacc[b][3] = __expf(sacc[b][3] - mn1);
                s0 += sacc[b][0] + sacc[b][1];
                s1 += sacc[b][2] + sacc[b][3];
            }
            s0 += __shfl_xor_sync(0xffffffffu, s0, 1);
            s0 += __shfl_xor_sync(0xffffffffu, s0, 2);
            s1 += __shfl_xor_sync(0xffffffffu, s1, 1);
            s1 += __shfl_xor_sync(0xffffffffu, s1, 2);
            l0 = l0 * f0 + s0;
            l1 = l1 * f1 + s1;

            #pragma unroll
            for (int nb = 0; nb < 16; nb++) {
                oacc[nb][0] *= f0; oacc[nb][1] *= f0;
                oacc[nb][2] *= f1; oacc[nb][3] *= f1;
            }

            // ---- pack P into fp16 A-fragments ----
            uint32_t ap[4][4];
            #pragma unroll
            for (int t = 0; t < 4; t++) {
                #pragma unroll
                for (int q = 0; q < 4; q++) {
                    const int blk = 2 * t + (q >> 1);
                    const int e0  = (q & 1) * 2;
                    ap[t][q] = packh2(__float2half_rn(sacc[blk][e0]),
                                      __float2half_rn(sacc[blk][e0 + 1]));
                }
            }

            // ---- O += P V (fp16 single-term) ----
            #pragma unroll
            for (int t = 0; t < 4; t++) {
                #pragma unroll
                for (int nb = 0; nb < 8; nb++) {
                    uint32_t vaddr = sbase +
                        (uint32_t)(kvb + AMAT +
                                   (t * 16 + (lane & 15)) * ASTR + nb * 16 + 8 * (lane >> 4)) * 2;
                    uint32_t vf[4];
                    ldsm4t(vf[0], vf[1], vf[2], vf[3], vaddr);
                    mma16816h(oacc[2 * nb],     ap[t], vf[0], vf[1]);
                    mma16816h(oacc[2 * nb + 1], ap[t], vf[2], vf[3]);
                }
            }
        }
        __syncthreads();
    }

    // ---- epilogue: normalize, write fp16 ----
    const float inv0 = 1.f / l0, inv1 = 1.f / l1;
    #pragma unroll
    for (int nb = 0; nb < 16; nb++) {
        const int col = nb * 8 + 2 * (lane & 3);
        size_t i0 = ((size_t)(qrow0 + r) * NH + h) * HD + col;
        size_t i1 = ((size_t)(qrow0 + r + 8) * NH + h) * HD + col;
        *(uint32_t*)(g_ao16 + i0) = packh2(
            __float2half_rn(oacc[nb][0] * inv0), __float2half_rn(oacc[nb][1] * inv0));
        *(uint32_t*)(g_ao16 + i1) = packh2(
            __float2half_rn(oacc[nb][2] * inv1), __float2half_rn(oacc[nb][3] * inv1));
    }
}

// ---------------------------------------------------------------------------
// kernel_launch
// ---------------------------------------------------------------------------
extern "C" void kernel_launch(void* const* d_in, const int* in_sizes, int n_in,
                              void* d_out, int out_size)
{
    const float* hidden = (const float*)d_in[0];
    const float* cosp   = (const float*)d_in[1];
    const float* sinp   = (const float*)d_in[2];
    const float* Wq     = (const float*)d_in[3];
    const float* Wk     = (const float*)d_in[4];
    const float* Wv     = (const float*)d_in[5];
    const float* Wo     = (const float*)d_in[6];
    const float* qw     = (const float*)d_in[7];
    const float* kw     = (const float*)d_in[8];
    float* out = (float*)d_out;

    float *qb, *kb;
    cudaGetSymbolAddress((void**)&qb, g_q);
    cudaGetSymbolAddress((void**)&kb, g_k);
    __half *hid16, *wq16, *wk16, *wv16, *wo16, *v16, *ao16;
    cudaGetSymbolAddress((void**)&hid16, g_hid16);
    cudaGetSymbolAddress((void**)&wq16,  g_wq16);
    cudaGetSymbolAddress((void**)&wk16,  g_wk16);
    cudaGetSymbolAddress((void**)&wv16,  g_wv16);
    cudaGetSymbolAddress((void**)&wo16,  g_wo16);
    cudaGetSymbolAddress((void**)&v16,   g_v16);
    cudaGetSymbolAddress((void**)&ao16,  g_ao16);

    // fp16 conversions
    {
        int n;
        n = S_LEN * HID;      cvt_f16<<<n / 1024, 256>>>(hidden, hid16, n);
        n = NH * HD * HID;    cvt_f16<<<n / 1024, 256>>>(Wq, wq16, n);
        n = NKV * HD * HID;   cvt_f16<<<n / 1024, 256>>>(Wk, wk16, n);
        n = NKV * HD * HID;   cvt_f16<<<n / 1024, 256>>>(Wv, wv16, n);
        n = HID * NH * HD;    cvt_f16<<<n / 1024, 256>>>(Wo, wo16, n);
    }

    cudaFuncSetAttribute(gemm_f16<float>, cudaFuncAttributeMaxDynamicSharedMemorySize, FSMEM);
    cudaFuncSetAttribute(gemm_f16<__half>, cudaFuncAttributeMaxDynamicSharedMemorySize, FSMEM);

    // QKV projections
    gemm_f16<float><<<dim3(NH * HD / 128,  S_LEN / 128), 256, FSMEM>>>(
        hid16, wq16, qb, S_LEN, NH * HD,  HID);
    gemm_f16<float><<<dim3(NKV * HD / 128, S_LEN / 128), 256, FSMEM>>>(
        hid16, wk16, kb, S_LEN, NKV * HD, HID);
    gemm_f16<__half><<<dim3(NKV * HD / 128, S_LEN / 128), 256, FSMEM>>>(
        hid16, wv16, v16, S_LEN, NKV * HD, HID);

    // RMSNorm + RoPE -> fp16 Q/K
    norm_rope_kernel<<<S_LEN * (NH + NKV), 128>>>(cosp, sinp, qw, kw);

    // fp16 causal flash attention
    cudaFuncSetAttribute(attn_mma_kernel, cudaFuncAttributeMaxDynamicSharedMemorySize, ATT_SMEM);
    attn_mma_kernel<<<dim3(S_LEN / 128, NH), 256, ATT_SMEM>>>();

    // O projection -> d_out
    gemm_f16<float><<<dim3(HID / 128, S_LEN / 128), 256, FSMEM>>>(
        ao16, wo16, out, S_LEN, HID, NH * HD);
}